// round 3
// baseline (speedup 1.0000x reference)
#include <cuda_runtime.h>
#include <math.h>

#define B_SZ   1024
#define H_SZ   200
#define E_SZ   256
#define R_SZ   256
#define HID_SZ 512
#define LN_EPS 1e-5f

// -------------------- scratch (device globals; no cudaMalloc allowed) ------
__device__ float g_msgs[(size_t)B_SZ * H_SZ * E_SZ];   // 209.7 MB messages
__device__ float g_qrepr[B_SZ * E_SZ];
__device__ float g_combined[B_SZ * 4 * E_SZ];
__device__ float g_h1[B_SZ * 2 * E_SZ];

// -------------------- helpers ----------------------------------------------
__device__ __forceinline__ float warpReduceSum(float v) {
#pragma unroll
    for (int o = 16; o; o >>= 1) v += __shfl_xor_sync(0xffffffffu, v, o);
    return v;
}
__device__ __forceinline__ float warpReduceMax(float v) {
#pragma unroll
    for (int o = 16; o; o >>= 1) v = fmaxf(v, __shfl_xor_sync(0xffffffffu, v, o));
    return v;
}
__device__ __forceinline__ float gelu_exact(float x) {
    return 0.5f * x * (1.0f + erff(x * 0.70710678118654752f));
}

// Mask dtype sniffing: harness may marshal the bool mask as bool8/int32/float32.
// Deterministic given inputs (same data -> same mode every call).
// mode: 0 = bool8, 1 = int32, 2 = float32
__device__ __forceinline__ int detect_mask_mode(const void* m) {
    const unsigned char* u = (const unsigned char*)m;
    const float* f = (const float*)m;
    bool is_i = true, is_f = true;
#pragma unroll
    for (int i = 0; i < 16; i++) {
        if (u[4 * i + 1] | u[4 * i + 2] | u[4 * i + 3]) is_i = false;
        float v = f[i];
        if (v != 0.0f && v != 1.0f) is_f = false;
    }
    if (is_i) return 1;   // int32 0/1 words (also covers all-zero ambiguity)
    if (is_f) return 2;   // exact 0.0/1.0 floats
    return 0;             // raw bool bytes
}
__device__ __forceinline__ float mask_val(const void* m, int idx, int mode) {
    if (mode == 1) return ((const int*)m)[idx] != 0 ? 1.f : 0.f;
    if (mode == 2) return ((const float*)m)[idx] != 0.f ? 1.f : 0.f;
    return ((const unsigned char*)m)[idx] ? 1.f : 0.f;
}

// ===========================================================================
// Kernel A: q_repr[b,e] = sum_k e_emb[b,k] * W_q[e,k]
// ===========================================================================
__global__ void __launch_bounds__(256) qrepr_kernel(const float* __restrict__ e_emb,
                                                    const float* __restrict__ Wq) {
    __shared__ float sx[E_SZ];
    const int b = blockIdx.x, tid = threadIdx.x;
    sx[tid] = e_emb[b * E_SZ + tid];
    __syncthreads();
    const int wid = tid >> 5, lane = tid & 31;
    const float4* sx4 = (const float4*)sx;
#pragma unroll 4
    for (int o = 0; o < 32; o++) {
        const int n = wid * 32 + o;
        const float4* w4 = (const float4*)(Wq + (size_t)n * E_SZ);
        float acc = 0.f;
#pragma unroll
        for (int i = 0; i < 2; i++) {
            float4 x = sx4[lane + i * 32];
            float4 w = w4[lane + i * 32];
            acc += x.x * w.x + x.y * w.y + x.z * w.z + x.w * w.w;
        }
        acc = warpReduceSum(acc);
        if (lane == 0) g_qrepr[b * E_SZ + n] = acc;
    }
}

// ===========================================================================
// Kernel B: messages[bh,e] = ent[bh,e] * (rel[bh,:] . W_rel[e,:])
// Classic 128x128x16 fp32 tiled GEMM, M=204800, N=256, K=256
// ===========================================================================
#define BM 128
#define BN 128
#define BK 16
#define PAD 4
__global__ void __launch_bounds__(256) gemm_msgs_kernel(const float* __restrict__ rel,
                                                        const float* __restrict__ Wr,
                                                        const float* __restrict__ ent) {
    __shared__ float As[BK * (BM + PAD)];
    __shared__ float Bs[BK * (BN + PAD)];
    const int tid = threadIdx.x;
    const int tx = tid & 15;        // n-dir (8 cols each)
    const int ty = tid >> 4;        // m-dir (8 rows each)
    const int lr = tid >> 2;        // load row 0..63
    const int lc = (tid & 3) * 4;   // load col {0,4,8,12}

    const float* Abase = rel + (size_t)blockIdx.y * BM * R_SZ;
    const float* Bbase = Wr  + (size_t)blockIdx.x * BN * R_SZ;

    float acc[8][8];
#pragma unroll
    for (int i = 0; i < 8; i++)
#pragma unroll
        for (int j = 0; j < 8; j++) acc[i][j] = 0.f;

    for (int k0 = 0; k0 < R_SZ; k0 += BK) {
#pragma unroll
        for (int i = 0; i < 2; i++) {
            const int row = lr + i * 64;
            float4 a = *(const float4*)(Abase + (size_t)row * R_SZ + k0 + lc);
            As[(lc + 0) * (BM + PAD) + row] = a.x;
            As[(lc + 1) * (BM + PAD) + row] = a.y;
            As[(lc + 2) * (BM + PAD) + row] = a.z;
            As[(lc + 3) * (BM + PAD) + row] = a.w;
            float4 w = *(const float4*)(Bbase + (size_t)row * R_SZ + k0 + lc);
            Bs[(lc + 0) * (BN + PAD) + row] = w.x;
            Bs[(lc + 1) * (BN + PAD) + row] = w.y;
            Bs[(lc + 2) * (BN + PAD) + row] = w.z;
            Bs[(lc + 3) * (BN + PAD) + row] = w.w;
        }
        __syncthreads();
#pragma unroll
        for (int k = 0; k < BK; k++) {
            float af[8], bf[8];
            *(float4*)&af[0] = *(const float4*)&As[k * (BM + PAD) + ty * 8];
            *(float4*)&af[4] = *(const float4*)&As[k * (BM + PAD) + ty * 8 + 4];
            *(float4*)&bf[0] = *(const float4*)&Bs[k * (BN + PAD) + tx * 8];
            *(float4*)&bf[4] = *(const float4*)&Bs[k * (BN + PAD) + tx * 8 + 4];
#pragma unroll
            for (int i = 0; i < 8; i++)
#pragma unroll
                for (int j = 0; j < 8; j++) acc[i][j] += af[i] * bf[j];
        }
        __syncthreads();
    }

#pragma unroll
    for (int i = 0; i < 8; i++) {
        const size_t row = (size_t)blockIdx.y * BM + ty * 8 + i;
        const size_t base = row * E_SZ + blockIdx.x * BN + tx * 8;
        float4 e0 = *(const float4*)(ent + base);
        float4 e1 = *(const float4*)(ent + base + 4);
        float4 r0 = make_float4(acc[i][0] * e0.x, acc[i][1] * e0.y,
                                acc[i][2] * e0.z, acc[i][3] * e0.w);
        float4 r1 = make_float4(acc[i][4] * e1.x, acc[i][5] * e1.y,
                                acc[i][6] * e1.z, acc[i][7] * e1.w);
        *(float4*)(g_msgs + base)     = r0;
        *(float4*)(g_msgs + base + 4) = r1;
    }
}

// ===========================================================================
// Kernel C: per-batch attention + PNA aggregation (msg tile in smem)
// ===========================================================================
__global__ void __launch_bounds__(256) aggregate_kernel(const float* __restrict__ e_emb,
                                                        const int* __restrict__ htime,
                                                        const int* __restrict__ qtime,
                                                        const void* __restrict__ maskp,
                                                        const float* __restrict__ log_gamma) {
    extern __shared__ float smsg[];            // [H_SZ * E_SZ]
    __shared__ float s_q[E_SZ];
    __shared__ float s_att[H_SZ];
    __shared__ float s_mask[H_SZ];
    __shared__ float s_red[8];
    __shared__ float s_b0, s_b1, s_b2;
    __shared__ int s_mode;

    const int b = blockIdx.x, tid = threadIdx.x;
    const int wid = tid >> 5, lane = tid & 31;

    if (tid == 0) s_mode = detect_mask_mode(maskp);

    const float4* gm4 = (const float4*)(g_msgs + (size_t)b * H_SZ * E_SZ);
    float4* sm4 = (float4*)smsg;
    const int n4 = H_SZ * E_SZ / 4;            // 12800
    for (int i = tid; i < n4; i += 256) sm4[i] = gm4[i];
    s_q[tid] = g_qrepr[b * E_SZ + tid];
    __syncthreads();
    if (tid < H_SZ) s_mask[tid] = mask_val(maskp, b * H_SZ + tid, s_mode);
    __syncthreads();

    // attention logits: warp-per-h dot(q, msgs[h]) * decay / sqrt(E), masked
    const float qt = (float)qtime[b];
    const float gamma = expf(log_gamma[0]);
    for (int h = wid; h < H_SZ; h += 8) {
        float acc = 0.f;
        const float4* m4 = (const float4*)(smsg + h * E_SZ);
        const float4* q4 = (const float4*)s_q;
#pragma unroll
        for (int i = 0; i < 2; i++) {
            float4 m = m4[lane + i * 32];
            float4 q = q4[lane + i * 32];
            acc += m.x * q.x + m.y * q.y + m.z * q.z + m.w * q.w;
        }
        acc = warpReduceSum(acc);
        if (lane == 0) {
            float td  = fmaxf(qt - (float)htime[b * H_SZ + h], 0.f);
            float dec = expf(-gamma * td);
            s_att[h]  = (s_mask[h] != 0.f) ? acc * dec * 0.0625f : -1e9f;
        }
    }
    __syncthreads();

    // softmax over H (block reduce) + n_valid count
    float v = (tid < H_SZ) ? s_att[tid] : -INFINITY;
    {
        float m = warpReduceMax(v);
        if (lane == 0) s_red[wid] = m;
        __syncthreads();
        if (tid < 32) {
            float t = (lane < 8) ? s_red[lane] : -INFINITY;
            t = warpReduceMax(t);
            if (lane == 0) s_b0 = t;
        }
        __syncthreads();
    }
    const float mx = s_b0;
    float ex = (tid < H_SZ) ? expf(v - mx) : 0.f;
    float nvp = (tid < H_SZ) ? s_mask[tid] : 0.f;
    {
        float s = warpReduceSum(ex);
        float c = warpReduceSum(nvp);
        if (lane == 0) s_red[wid] = s;
        __syncthreads();
        if (tid < 32) {
            float t = (lane < 8) ? s_red[lane] : 0.f;
            t = warpReduceSum(t);
            if (lane == 0) s_b1 = t;
        }
        __syncthreads();
        if (lane == 0) s_red[wid] = c;
        __syncthreads();
        if (tid < 32) {
            float t = (lane < 8) ? s_red[lane] : 0.f;
            t = warpReduceSum(t);
            if (lane == 0) s_b2 = t;
        }
        __syncthreads();
    }
    const float inv_sum = 1.0f / s_b1;
    const float nv = fmaxf(s_b2, 1.0f);
    if (tid < H_SZ) s_att[tid] = ex * inv_sum;
    __syncthreads();

    // PNA reductions: thread = e channel
    float mean = 0.f, mxv = -INFINITY, am = 0.f;
#pragma unroll 4
    for (int h = 0; h < H_SZ; h++) {
        float val = smsg[h * E_SZ + tid];
        float mk  = s_mask[h];
        float vm  = val * mk;
        mean += vm;
        mxv = fmaxf(mxv, vm);
        am += s_att[h] * val;
    }
    float* outr = g_combined + (size_t)b * 4 * E_SZ;
    outr[tid]             = mean / nv;
    outr[E_SZ + tid]      = mxv;
    outr[2 * E_SZ + tid]  = am;
    outr[3 * E_SZ + tid]  = e_emb[b * E_SZ + tid];
}

// ===========================================================================
// Kernel D: h1 = gelu(LN(combined @ W1^T + b1))   (B,1024)->(B,512)
// ===========================================================================
__global__ void __launch_bounds__(512) mlp1_kernel(const float* __restrict__ W1,
                                                   const float* __restrict__ b1,
                                                   const float* __restrict__ g1,
                                                   const float* __restrict__ be1) {
    __shared__ float sx[4 * E_SZ];
    __shared__ float sh[2 * E_SZ];
    __shared__ float s_red[16];
    __shared__ float s_b;
    const int b = blockIdx.x, tid = threadIdx.x;
    const int wid = tid >> 5, lane = tid & 31;

    const float4* cx4 = (const float4*)(g_combined + (size_t)b * 4 * E_SZ);
    float4* sx4 = (float4*)sx;
    for (int i = tid; i < 256; i += 512) sx4[i] = cx4[i];
    __syncthreads();

#pragma unroll 2
    for (int o = 0; o < 32; o++) {
        const int n = wid * 32 + o;
        const float4* w4 = (const float4*)(W1 + (size_t)n * 1024);
        float acc = 0.f;
#pragma unroll
        for (int i = 0; i < 8; i++) {
            float4 x = ((const float4*)sx)[lane + i * 32];
            float4 w = w4[lane + i * 32];
            acc += x.x * w.x + x.y * w.y + x.z * w.z + x.w * w.w;
        }
        acc = warpReduceSum(acc);
        if (lane == 0) sh[n] = acc + b1[n];
    }
    __syncthreads();

    float x = sh[tid];
    float s = warpReduceSum(x);
    if (lane == 0) s_red[wid] = s;
    __syncthreads();
    if (tid < 32) {
        float t = (lane < 16) ? s_red[lane] : 0.f;
        t = warpReduceSum(t);
        if (lane == 0) s_b = t;
    }
    __syncthreads();
    const float mu = s_b / 512.f;
    const float d = x - mu;
    float s2 = warpReduceSum(d * d);
    if (lane == 0) s_red[wid] = s2;
    __syncthreads();
    if (tid < 32) {
        float t = (lane < 16) ? s_red[lane] : 0.f;
        t = warpReduceSum(t);
        if (lane == 0) s_b = t;
    }
    __syncthreads();
    const float var = s_b / 512.f;
    float y = d * rsqrtf(var + LN_EPS) * g1[tid] + be1[tid];
    g_h1[(size_t)b * 512 + tid] = gelu_exact(y);
}

// ===========================================================================
// Kernel E: dynamic_emb = LN(h1 @ W2^T + b2)  (B,512)->(B,256) -> d_out
// ===========================================================================
__global__ void __launch_bounds__(256) mlp2_kernel(const float* __restrict__ W2,
                                                   const float* __restrict__ b2,
                                                   const float* __restrict__ g2,
                                                   const float* __restrict__ be2,
                                                   float* __restrict__ out) {
    __shared__ float sx[2 * E_SZ];
    __shared__ float sh[E_SZ];
    __shared__ float s_red[8];
    __shared__ float s_b;
    const int b = blockIdx.x, tid = threadIdx.x;
    const int wid = tid >> 5, lane = tid & 31;

    const float4* hx4 = (const float4*)(g_h1 + (size_t)b * 512);
    float4* sx4 = (float4*)sx;
    for (int i = tid; i < 128; i += 256) sx4[i] = hx4[i];
    __syncthreads();

#pragma unroll 2
    for (int o = 0; o < 32; o++) {
        const int n = wid * 32 + o;
        const float4* w4 = (const float4*)(W2 + (size_t)n * 512);
        float acc = 0.f;
#pragma unroll
        for (int i = 0; i < 4; i++) {
            float4 x = ((const float4*)sx)[lane + i * 32];
            float4 w = w4[lane + i * 32];
            acc += x.x * w.x + x.y * w.y + x.z * w.z + x.w * w.w;
        }
        acc = warpReduceSum(acc);
        if (lane == 0) sh[n] = acc + b2[n];
    }
    __syncthreads();

    float x = sh[tid];
    float s = warpReduceSum(x);
    if (lane == 0) s_red[wid] = s;
    __syncthreads();
    if (tid < 32) {
        float t = (lane < 8) ? s_red[lane] : 0.f;
        t = warpReduceSum(t);
        if (lane == 0) s_b = t;
    }
    __syncthreads();
    const float mu = s_b / 256.f;
    const float d = x - mu;
    float s2 = warpReduceSum(d * d);
    if (lane == 0) s_red[wid] = s2;
    __syncthreads();
    if (tid < 32) {
        float t = (lane < 8) ? s_red[lane] : 0.f;
        t = warpReduceSum(t);
        if (lane == 0) s_b = t;
    }
    __syncthreads();
    const float var = s_b / 256.f;
    out[(size_t)b * E_SZ + tid] = d * rsqrtf(var + LN_EPS) * g2[tid] + be2[tid];
}

// ===========================================================================
// Kernel F: ctx = gelu(LN(dyn @ Wc^T + bc))  (B,256)->(B,512) -> d_out[B*E..]
// ===========================================================================
__global__ void __launch_bounds__(512) ctx_kernel(const float* __restrict__ Wc,
                                                  const float* __restrict__ bc,
                                                  const float* __restrict__ gc,
                                                  const float* __restrict__ bec,
                                                  float* __restrict__ out) {
    __shared__ float sx[E_SZ];
    __shared__ float sh[HID_SZ];
    __shared__ float s_red[16];
    __shared__ float s_b;
    const int b = blockIdx.x, tid = threadIdx.x;
    const int wid = tid >> 5, lane = tid & 31;

    const float* dyn = out + (size_t)b * E_SZ;
    if (tid < E_SZ) sx[tid] = dyn[tid];
    __syncthreads();

#pragma unroll 2
    for (int o = 0; o < 32; o++) {
        const int n = wid * 32 + o;
        const float4* w4 = (const float4*)(Wc + (size_t)n * E_SZ);
        float acc = 0.f;
#pragma unroll
        for (int i = 0; i < 2; i++) {
            float4 x = ((const float4*)sx)[lane + i * 32];
            float4 w = w4[lane + i * 32];
            acc += x.x * w.x + x.y * w.y + x.z * w.z + x.w * w.w;
        }
        acc = warpReduceSum(acc);
        if (lane == 0) sh[n] = acc + bc[n];
    }
    __syncthreads();

    float x = sh[tid];
    float s = warpReduceSum(x);
    if (lane == 0) s_red[wid] = s;
    __syncthreads();
    if (tid < 32) {
        float t = (lane < 16) ? s_red[lane] : 0.f;
        t = warpReduceSum(t);
        if (lane == 0) s_b = t;
    }
    __syncthreads();
    const float mu = s_b / 512.f;
    const float d = x - mu;
    float s2 = warpReduceSum(d * d);
    if (lane == 0) s_red[wid] = s2;
    __syncthreads();
    if (tid < 32) {
        float t = (lane < 16) ? s_red[lane] : 0.f;
        t = warpReduceSum(t);
        if (lane == 0) s_b = t;
    }
    __syncthreads();
    const float var = s_b / 512.f;
    float y = d * rsqrtf(var + LN_EPS) * gc[tid] + bec[tid];
    out[(size_t)B_SZ * E_SZ + (size_t)b * HID_SZ + tid] = gelu_exact(y);
}

// ===========================================================================
extern "C" void kernel_launch(void* const* d_in, const int* in_sizes, int n_in,
                              void* d_out, int out_size) {
    const float* e_emb     = (const float*)d_in[0];
    const float* ent       = (const float*)d_in[1];   // hist_ent_emb
    const float* rel       = (const float*)d_in[2];   // hist_rel_emb
    const int*   htime     = (const int*)d_in[3];
    const int*   qtime     = (const int*)d_in[4];
    const void*  maskp     = (const void*)d_in[5];
    const float* W_rel     = (const float*)d_in[6];
    const float* W_q       = (const float*)d_in[7];
    const float* log_gamma = (const float*)d_in[8];
    const float* W1        = (const float*)d_in[9];
    const float* b1        = (const float*)d_in[10];
    const float* ln1_g     = (const float*)d_in[11];
    const float* ln1_b     = (const float*)d_in[12];
    const float* W2        = (const float*)d_in[13];
    const float* b2        = (const float*)d_in[14];
    const float* ln2_g     = (const float*)d_in[15];
    const float* ln2_b     = (const float*)d_in[16];
    const float* Wc        = (const float*)d_in[17];
    const float* bc        = (const float*)d_in[18];
    const float* lnc_g     = (const float*)d_in[19];
    const float* lnc_b     = (const float*)d_in[20];
    float* out = (float*)d_out;

    cudaFuncSetAttribute(aggregate_kernel,
                         cudaFuncAttributeMaxDynamicSharedMemorySize,
                         H_SZ * E_SZ * (int)sizeof(float));

    qrepr_kernel<<<B_SZ, 256>>>(e_emb, W_q);

    dim3 gridB(E_SZ / BN, (B_SZ * H_SZ) / BM);   // (2, 1600)
    gemm_msgs_kernel<<<gridB, 256>>>(rel, W_rel, ent);

    aggregate_kernel<<<B_SZ, 256, H_SZ * E_SZ * (int)sizeof(float)>>>(
        e_emb, htime, qtime, maskp, log_gamma);

    mlp1_kernel<<<B_SZ, 512>>>(W1, b1, ln1_g, ln1_b);
    mlp2_kernel<<<B_SZ, 256>>>(W2, b2, ln2_g, ln2_b, out);
    ctx_kernel<<<B_SZ, 512>>>(Wc, bc, lnc_g, lnc_b, out);
}

// round 6
// speedup vs baseline: 1.6713x; 1.6713x over previous
#include <cuda_runtime.h>
#include <cuda_bf16.h>
#include <math.h>
#include <stdint.h>

#define B_SZ   1024
#define H_SZ   200
#define E_SZ   256
#define R_SZ   256
#define HID_SZ 512
#define LN_EPS 1e-5f

// -------------------- scratch (device globals; no cudaMalloc allowed) ------
__device__ float g_msgs[(size_t)B_SZ * H_SZ * E_SZ];   // 209.7 MB messages
__device__ float g_qrepr[B_SZ * E_SZ];
__device__ float g_combined[B_SZ * 4 * E_SZ];
__device__ float g_h1[B_SZ * 2 * E_SZ];
__device__ __nv_bfloat16 g_w_hi[E_SZ * R_SZ];
__device__ __nv_bfloat16 g_w_lo[E_SZ * R_SZ];

// -------------------- helpers ----------------------------------------------
__device__ __forceinline__ uint32_t smem_to_u32(const void* p) {
    uint32_t a;
    asm("{ .reg .u64 t; cvta.to.shared.u64 t, %1; cvt.u32.u64 %0, t; }"
        : "=r"(a) : "l"(p));
    return a;
}
#define SMEM_SWIZZLE_128B(o) ((o) ^ (((o) >> 3) & 0x70))

#define LDSM_X4(r, a) \
    asm volatile("ldmatrix.sync.aligned.m8n8.x4.shared.b16 {%0,%1,%2,%3}, [%4];" \
                 : "=r"((r)[0]), "=r"((r)[1]), "=r"((r)[2]), "=r"((r)[3]) \
                 : "r"(a))

#define MMA_BF16(c, a, b0, b1) \
    asm volatile("mma.sync.aligned.m16n8k16.row.col.f32.bf16.bf16.f32 " \
                 "{%0,%1,%2,%3}, {%4,%5,%6,%7}, {%8,%9}, {%0,%1,%2,%3};" \
                 : "+f"((c)[0]), "+f"((c)[1]), "+f"((c)[2]), "+f"((c)[3]) \
                 : "r"((a)[0]), "r"((a)[1]), "r"((a)[2]), "r"((a)[3]), \
                   "r"(b0), "r"(b1))

__device__ __forceinline__ float warpReduceSum(float v) {
#pragma unroll
    for (int o = 16; o; o >>= 1) v += __shfl_xor_sync(0xffffffffu, v, o);
    return v;
}
__device__ __forceinline__ float warpReduceMax(float v) {
#pragma unroll
    for (int o = 16; o; o >>= 1) v = fmaxf(v, __shfl_xor_sync(0xffffffffu, v, o));
    return v;
}
__device__ __forceinline__ float gelu_exact(float x) {
    return 0.5f * x * (1.0f + erff(x * 0.70710678118654752f));
}
__device__ __forceinline__ int detect_mask_mode(const void* m) {
    const unsigned char* u = (const unsigned char*)m;
    const float* f = (const float*)m;
    bool is_i = true, is_f = true;
#pragma unroll
    for (int i = 0; i < 16; i++) {
        if (u[4 * i + 1] | u[4 * i + 2] | u[4 * i + 3]) is_i = false;
        float v = f[i];
        if (v != 0.0f && v != 1.0f) is_f = false;
    }
    if (is_i) return 1;
    if (is_f) return 2;
    return 0;
}
__device__ __forceinline__ float mask_val(const void* m, int idx, int mode) {
    if (mode == 1) return ((const int*)m)[idx] != 0 ? 1.f : 0.f;
    if (mode == 2) return ((const float*)m)[idx] != 0.f ? 1.f : 0.f;
    return ((const unsigned char*)m)[idx] ? 1.f : 0.f;
}
__device__ __forceinline__ unsigned pack_bf2(__nv_bfloat16 a, __nv_bfloat16 b) {
    __nv_bfloat162 t(a, b);
    return *reinterpret_cast<unsigned*>(&t);
}

// ===========================================================================
// Kernel 0: fp32 -> bf16 hi/lo split (W_rel only; 64K elements)
// ===========================================================================
__global__ void __launch_bounds__(256) conv_split_kernel(const float* __restrict__ src,
                                                         __nv_bfloat16* __restrict__ hi,
                                                         __nv_bfloat16* __restrict__ lo,
                                                         size_t n4) {
    size_t i = (size_t)blockIdx.x * 256 + threadIdx.x;
    const size_t stride = (size_t)gridDim.x * 256;
    for (; i < n4; i += stride) {
        float4 x = ((const float4*)src)[i];
        __nv_bfloat16 h0 = __float2bfloat16(x.x);
        __nv_bfloat16 h1 = __float2bfloat16(x.y);
        __nv_bfloat16 h2 = __float2bfloat16(x.z);
        __nv_bfloat16 h3 = __float2bfloat16(x.w);
        __nv_bfloat16 l0 = __float2bfloat16(x.x - __bfloat162float(h0));
        __nv_bfloat16 l1 = __float2bfloat16(x.y - __bfloat162float(h1));
        __nv_bfloat16 l2 = __float2bfloat16(x.z - __bfloat162float(h2));
        __nv_bfloat16 l3 = __float2bfloat16(x.w - __bfloat162float(h3));
        ((uint2*)hi)[i] = make_uint2(pack_bf2(h0, h1), pack_bf2(h2, h3));
        ((uint2*)lo)[i] = make_uint2(pack_bf2(l0, l1), pack_bf2(l2, l3));
    }
}

// ===========================================================================
// Kernel A: q_repr[b,e] = sum_k e_emb[b,k] * W_q[e,k]
// ===========================================================================
__global__ void __launch_bounds__(256) qrepr_kernel(const float* __restrict__ e_emb,
                                                    const float* __restrict__ Wq) {
    __shared__ float sx[E_SZ];
    const int b = blockIdx.x, tid = threadIdx.x;
    sx[tid] = e_emb[b * E_SZ + tid];
    __syncthreads();
    const int wid = tid >> 5, lane = tid & 31;
    const float4* sx4 = (const float4*)sx;
#pragma unroll 4
    for (int o = 0; o < 32; o++) {
        const int n = wid * 32 + o;
        const float4* w4 = (const float4*)(Wq + (size_t)n * E_SZ);
        float acc = 0.f;
#pragma unroll
        for (int i = 0; i < 2; i++) {
            float4 x = sx4[lane + i * 32];
            float4 w = w4[lane + i * 32];
            acc += x.x * w.x + x.y * w.y + x.z * w.z + x.w * w.w;
        }
        acc = warpReduceSum(acc);
        if (lane == 0) g_qrepr[b * E_SZ + n] = acc;
    }
}

// ===========================================================================
// Kernel B (HMMA): messages[m,e] = ent[m,e] * (rel[m,:] . W_rel[e,:])
// mma.sync m16n8k16 bf16, 3-term hi/lo split, fp32 accum in registers.
// CTA = 128(M) x 256(N=full E), BK=64, 512 threads (16 warps, 4m x 4n),
// warp tile 32x64. A fp32->bf16 split fused into the tile load.
// ===========================================================================
#define O_AH 0
#define O_AL 16384
#define O_BH 32768
#define O_BL 65536
#define SM_HMMA 98304

__global__ void __launch_bounds__(512, 1) gemm_msgs_hmma(const float* __restrict__ rel,
                                                         const float* __restrict__ ent) {
    extern __shared__ char sm[];
    const uint32_t smb = smem_to_u32(sm);
    const int tid = threadIdx.x;
    const int warp = tid >> 5, lane = tid & 31;
    const int wm = warp & 3, wn = warp >> 2;     // 4 x 4 warp grid
    const int m0 = blockIdx.x * 128;

    float acc[2][8][4];
#pragma unroll
    for (int i = 0; i < 2; i++)
#pragma unroll
        for (int j = 0; j < 8; j++)
#pragma unroll
            for (int q = 0; q < 4; q++) acc[i][j][q] = 0.f;

    const char* whp = (const char*)g_w_hi;
    const char* wlp = (const char*)g_w_lo;

    for (int s = 0; s < 4; s++) {
        // ---- A tile: 128 rows x 64 cols fp32 -> bf16 hi/lo smem (SW128) ----
        const float* asrc = rel + (size_t)m0 * R_SZ + s * 64;
#pragma unroll
        for (int j = 0; j < 4; j++) {
            const int idx = tid + j * 512;       // 0..2047 float4s
            const int row = idx >> 4, c4 = idx & 15;
            float4 x = *(const float4*)(asrc + (size_t)row * R_SZ + c4 * 4);
            __nv_bfloat16 h0 = __float2bfloat16(x.x);
            __nv_bfloat16 h1 = __float2bfloat16(x.y);
            __nv_bfloat16 h2 = __float2bfloat16(x.z);
            __nv_bfloat16 h3 = __float2bfloat16(x.w);
            __nv_bfloat16 l0 = __float2bfloat16(x.x - __bfloat162float(h0));
            __nv_bfloat16 l1 = __float2bfloat16(x.y - __bfloat162float(h1));
            __nv_bfloat16 l2 = __float2bfloat16(x.z - __bfloat162float(h2));
            __nv_bfloat16 l3 = __float2bfloat16(x.w - __bfloat162float(h3));
            const int bo = SMEM_SWIZZLE_128B(row * 128 + c4 * 8);
            *(uint2*)(sm + O_AH + bo) = make_uint2(pack_bf2(h0, h1), pack_bf2(h2, h3));
            *(uint2*)(sm + O_AL + bo) = make_uint2(pack_bf2(l0, l1), pack_bf2(l2, l3));
        }
        // ---- B tiles: 256 rows x 64 bf16 from pre-split W (SW128) ----------
        const size_t bsrc = (size_t)s * 128;     // byte offset of k-chunk in 512B row
#pragma unroll
        for (int j = 0; j < 4; j++) {
            const int idx = tid + j * 512;       // 0..2047 16B-chunks
            const int row = idx >> 3, ch = idx & 7;
            const size_t so = bsrc + (size_t)row * 512 + ch * 16;
            const int bo = SMEM_SWIZZLE_128B(row * 128 + ch * 16);
            *(uint4*)(sm + O_BH + bo) = *(const uint4*)(whp + so);
            *(uint4*)(sm + O_BL + bo) = *(const uint4*)(wlp + so);
        }
        __syncthreads();

        // ---- compute: 4 k16 steps ------------------------------------------
#pragma unroll
        for (int kk = 0; kk < 4; kk++) {
            uint32_t ah[2][4], al[2][4];
#pragma unroll
            for (int mt = 0; mt < 2; mt++) {
                const int arow = wm * 32 + mt * 16 + (lane & 15);
                const int aoff = SMEM_SWIZZLE_128B(arow * 128 + kk * 32 + ((lane >> 4) & 1) * 16);
                LDSM_X4(ah[mt], smb + O_AH + aoff);
                LDSM_X4(al[mt], smb + O_AL + aoff);
            }
#pragma unroll
            for (int np = 0; np < 4; np++) {
                const int nrow = wn * 64 + np * 16 + (lane & 7) + ((lane >> 4) & 1) * 8;
                const int boff = SMEM_SWIZZLE_128B(nrow * 128 + kk * 32 + ((lane >> 3) & 1) * 16);
                uint32_t bh4[4], bl4[4];
                LDSM_X4(bh4, smb + O_BH + boff);
                LDSM_X4(bl4, smb + O_BL + boff);
#pragma unroll
                for (int mt = 0; mt < 2; mt++) {
#pragma unroll
                    for (int h = 0; h < 2; h++) {
                        float* c = acc[mt][np * 2 + h];
                        MMA_BF16(c, ah[mt], bh4[2 * h], bh4[2 * h + 1]);
                        MMA_BF16(c, ah[mt], bl4[2 * h], bl4[2 * h + 1]);
                        MMA_BF16(c, al[mt], bh4[2 * h], bh4[2 * h + 1]);
                    }
                }
            }
        }
        __syncthreads();
    }

    // ---- epilogue: x ent, store msgs --------------------------------------
    const int g = lane >> 2, tig = lane & 3;
#pragma unroll
    for (int mt = 0; mt < 2; mt++) {
        const int r0 = m0 + wm * 32 + mt * 16 + g;
#pragma unroll
        for (int nt = 0; nt < 8; nt++) {
            const int c = wn * 64 + nt * 8 + tig * 2;
            const size_t o1 = (size_t)r0 * E_SZ + c;
            const size_t o2 = o1 + 8 * E_SZ;
            float2 e1 = *(const float2*)(ent + o1);
            float2 e2 = *(const float2*)(ent + o2);
            *(float2*)(g_msgs + o1) = make_float2(acc[mt][nt][0] * e1.x,
                                                  acc[mt][nt][1] * e1.y);
            *(float2*)(g_msgs + o2) = make_float2(acc[mt][nt][2] * e2.x,
                                                  acc[mt][nt][3] * e2.y);
        }
    }
}

// ===========================================================================
// Kernel C: per-batch attention + PNA aggregation (msg tile in smem)
// ===========================================================================
__global__ void __launch_bounds__(256) aggregate_kernel(const float* __restrict__ e_emb,
                                                        const int* __restrict__ htime,
                                                        const int* __restrict__ qtime,
                                                        const void* __restrict__ maskp,
                                                        const float* __restrict__ log_gamma) {
    extern __shared__ float smsg[];            // [H_SZ * E_SZ]
    __shared__ float s_q[E_SZ];
    __shared__ float s_att[H_SZ];
    __shared__ float s_mask[H_SZ];
    __shared__ float s_red[8];
    __shared__ float s_b0, s_b1, s_b2;
    __shared__ int s_mode;

    const int b = blockIdx.x, tid = threadIdx.x;
    const int wid = tid >> 5, lane = tid & 31;

    if (tid == 0) s_mode = detect_mask_mode(maskp);

    const float4* gm4 = (const float4*)(g_msgs + (size_t)b * H_SZ * E_SZ);
    float4* sm4 = (float4*)smsg;
    const int n4 = H_SZ * E_SZ / 4;
    for (int i = tid; i < n4; i += 256) sm4[i] = gm4[i];
    s_q[tid] = g_qrepr[b * E_SZ + tid];
    __syncthreads();
    if (tid < H_SZ) s_mask[tid] = mask_val(maskp, b * H_SZ + tid, s_mode);
    __syncthreads();

    const float qt = (float)qtime[b];
    const float gamma = expf(log_gamma[0]);
    for (int h = wid; h < H_SZ; h += 8) {
        float acc = 0.f;
        const float4* m4 = (const float4*)(smsg + h * E_SZ);
        const float4* q4 = (const float4*)s_q;
#pragma unroll
        for (int i = 0; i < 2; i++) {
            float4 m = m4[lane + i * 32];
            float4 q = q4[lane + i * 32];
            acc += m.x * q.x + m.y * q.y + m.z * q.z + m.w * q.w;
        }
        acc = warpReduceSum(acc);
        if (lane == 0) {
            float td  = fmaxf(qt - (float)htime[b * H_SZ + h], 0.f);
            float dec = expf(-gamma * td);
            s_att[h]  = (s_mask[h] != 0.f) ? acc * dec * 0.0625f : -1e9f;
        }
    }
    __syncthreads();

    float v = (tid < H_SZ) ? s_att[tid] : -INFINITY;
    {
        float m = warpReduceMax(v);
        if (lane == 0) s_red[wid] = m;
        __syncthreads();
        if (tid < 32) {
            float t = (lane < 8) ? s_red[lane] : -INFINITY;
            t = warpReduceMax(t);
            if (lane == 0) s_b0 = t;
        }
        __syncthreads();
    }
    const float mx = s_b0;
    float ex = (tid < H_SZ) ? expf(v - mx) : 0.f;
    float nvp = (tid < H_SZ) ? s_mask[tid] : 0.f;
    {
        float s = warpReduceSum(ex);
        float c = warpReduceSum(nvp);
        if (lane == 0) s_red[wid] = s;
        __syncthreads();
        if (tid < 32) {
            float t = (lane < 8) ? s_red[lane] : 0.f;
            t = warpReduceSum(t);
            if (lane == 0) s_b1 = t;
        }
        __syncthreads();
        if (lane == 0) s_red[wid] = c;
        __syncthreads();
        if (tid < 32) {
            float t = (lane < 8) ? s_red[lane] : 0.f;
            t = warpReduceSum(t);
            if (lane == 0) s_b2 = t;
        }
        __syncthreads();
    }
    const float inv_sum = 1.0f / s_b1;
    const float nv = fmaxf(s_b2, 1.0f);
    if (tid < H_SZ) s_att[tid] = ex * inv_sum;
    __syncthreads();

    float mean = 0.f, mxv = -INFINITY, am = 0.f;
#pragma unroll 4
    for (int h = 0; h < H_SZ; h++) {
        float val = smsg[h * E_SZ + tid];
        float mk  = s_mask[h];
        float vm  = val * mk;
        mean += vm;
        mxv = fmaxf(mxv, vm);
        am += s_att[h] * val;
    }
    float* outr = g_combined + (size_t)b * 4 * E_SZ;
    outr[tid]             = mean / nv;
    outr[E_SZ + tid]      = mxv;
    outr[2 * E_SZ + tid]  = am;
    outr[3 * E_SZ + tid]  = e_emb[b * E_SZ + tid];
}

// ===========================================================================
// Kernel D: h1 = gelu(LN(combined @ W1^T + b1))   (B,1024)->(B,512)
// ===========================================================================
__global__ void __launch_bounds__(512) mlp1_kernel(const float* __restrict__ W1,
                                                   const float* __restrict__ b1,
                                                   const float* __restrict__ g1,
                                                   const float* __restrict__ be1) {
    __shared__ float sx[4 * E_SZ];
    __shared__ float sh[2 * E_SZ];
    __shared__ float s_red[16];
    __shared__ float s_b;
    const int b = blockIdx.x, tid = threadIdx.x;
    const int wid = tid >> 5, lane = tid & 31;

    const float4* cx4 = (const float4*)(g_combined + (size_t)b * 4 * E_SZ);
    float4* sx4 = (float4*)sx;
    for (int i = tid; i < 256; i += 512) sx4[i] = cx4[i];
    __syncthreads();

#pragma unroll 2
    for (int o = 0; o < 32; o++) {
        const int n = wid * 32 + o;
        const float4* w4 = (const float4*)(W1 + (size_t)n * 1024);
        float acc = 0.f;
#pragma unroll
        for (int i = 0; i < 8; i++) {
            float4 x = ((const float4*)sx)[lane + i * 32];
            float4 w = w4[lane + i * 32];
            acc += x.x * w.x + x.y * w.y + x.z * w.z + x.w * w.w;
        }
        acc = warpReduceSum(acc);
        if (lane == 0) sh[n] = acc + b1[n];
    }
    __syncthreads();

    float x = sh[tid];
    float s = warpReduceSum(x);
    if (lane == 0) s_red[wid] = s;
    __syncthreads();
    if (tid < 32) {
        float t = (lane < 16) ? s_red[lane] : 0.f;
        t = warpReduceSum(t);
        if (lane == 0) s_b = t;
    }
    __syncthreads();
    const float mu = s_b / 512.f;
    const float d = x - mu;
    float s2 = warpReduceSum(d * d);
    if (lane == 0) s_red[wid] = s2;
    __syncthreads();
    if (tid < 32) {
        float t = (lane < 16) ? s_red[lane] : 0.f;
        t = warpReduceSum(t);
        if (lane == 0) s_b = t;
    }
    __syncthreads();
    const float var = s_b / 512.f;
    float y = d * rsqrtf(var + LN_EPS) * g1[tid] + be1[tid];
    g_h1[(size_t)b * 512 + tid] = gelu_exact(y);
}

// ===========================================================================
// Kernel E: dynamic_emb = LN(h1 @ W2^T + b2)  (B,512)->(B,256) -> d_out
// ===========================================================================
__global__ void __launch_bounds__(256) mlp2_kernel(const float* __restrict__ W2,
                                                   const float* __restrict__ b2,
                                                   const float* __restrict__ g2,
                                                   const float* __restrict__ be2,
                                                   float* __restrict__ out) {
    __shared__ float sx[2 * E_SZ];
    __shared__ float sh[E_SZ];
    __shared__ float s_red[8];
    __shared__ float s_b;
    const int b = blockIdx.x, tid = threadIdx.x;
    const int wid = tid >> 5, lane = tid & 31;

    const float4* hx4 = (const float4*)(g_h1 + (size_t)b * 512);
    float4* sx4 = (float4*)sx;
    for (int i = tid; i < 128; i += 256) sx4[i] = hx4[i];
    __syncthreads();

#pragma unroll 2
    for (int o = 0; o < 32; o++) {
        const int n = wid * 32 + o;
        const float4* w4 = (const float4*)(W2 + (size_t)n * 512);
        float acc = 0.f;
#pragma unroll
        for (int i = 0; i < 4; i++) {
            float4 x = ((const float4*)sx)[lane + i * 32];
            float4 w = w4[lane + i * 32];
            acc += x.x * w.x + x.y * w.y + x.z * w.z + x.w * w.w;
        }
        acc = warpReduceSum(acc);
        if (lane == 0) sh[n] = acc + b2[n];
    }
    __syncthreads();

    float x = sh[tid];
    float s = warpReduceSum(x);
    if (lane == 0) s_red[wid] = s;
    __syncthreads();
    if (tid < 32) {
        float t = (lane < 8) ? s_red[lane] : 0.f;
        t = warpReduceSum(t);
        if (lane == 0) s_b = t;
    }
    __syncthreads();
    const float mu = s_b / 256.f;
    const float d = x - mu;
    float s2 = warpReduceSum(d * d);
    if (lane == 0) s_red[wid] = s2;
    __syncthreads();
    if (tid < 32) {
        float t = (lane < 8) ? s_red[lane] : 0.f;
        t = warpReduceSum(t);
        if (lane == 0) s_b = t;
    }
    __syncthreads();
    const float var = s_b / 256.f;
    out[(size_t)b * E_SZ + tid] = d * rsqrtf(var + LN_EPS) * g2[tid] + be2[tid];
}

// ===========================================================================
// Kernel F: ctx = gelu(LN(dyn @ Wc^T + bc))  (B,256)->(B,512) -> d_out[B*E..]
// ===========================================================================
__global__ void __launch_bounds__(512) ctx_kernel(const float* __restrict__ Wc,
                                                  const float* __restrict__ bc,
                                                  const float* __restrict__ gc,
                                                  const float* __restrict__ bec,
                                                  float* __restrict__ out) {
    __shared__ float sx[E_SZ];
    __shared__ float sh[HID_SZ];
    __shared__ float s_red[16];
    __shared__ float s_b;
    const int b = blockIdx.x, tid = threadIdx.x;
    const int wid = tid >> 5, lane = tid & 31;

    const float* dyn = out + (size_t)b * E_SZ;
    if (tid < E_SZ) sx[tid] = dyn[tid];
    __syncthreads();

#pragma unroll 2
    for (int o = 0; o < 32; o++) {
        const int n = wid * 32 + o;
        const float4* w4 = (const float4*)(Wc + (size_t)n * E_SZ);
        float acc = 0.f;
#pragma unroll
        for (int i = 0; i < 2; i++) {
            float4 x = ((const float4*)sx)[lane + i * 32];
            float4 w = w4[lane + i * 32];
            acc += x.x * w.x + x.y * w.y + x.z * w.z + x.w * w.w;
        }
        acc = warpReduceSum(acc);
        if (lane == 0) sh[n] = acc + bc[n];
    }
    __syncthreads();

    float x = sh[tid];
    float s = warpReduceSum(x);
    if (lane == 0) s_red[wid] = s;
    __syncthreads();
    if (tid < 32) {
        float t = (lane < 16) ? s_red[lane] : 0.f;
        t = warpReduceSum(t);
        if (lane == 0) s_b = t;
    }
    __syncthreads();
    const float mu = s_b / 512.f;
    const float d = x - mu;
    float s2 = warpReduceSum(d * d);
    if (lane == 0) s_red[wid] = s2;
    __syncthreads();
    if (tid < 32) {
        float t = (lane < 16) ? s_red[lane] : 0.f;
        t = warpReduceSum(t);
        if (lane == 0) s_b = t;
    }
    __syncthreads();
    const float var = s_b / 512.f;
    float y = d * rsqrtf(var + LN_EPS) * gc[tid] + bec[tid];
    out[(size_t)B_SZ * E_SZ + (size_t)b * HID_SZ + tid] = gelu_exact(y);
}

// ===========================================================================
extern "C" void kernel_launch(void* const* d_in, const int* in_sizes, int n_in,
                              void* d_out, int out_size) {
    const float* e_emb     = (const float*)d_in[0];
    const float* ent       = (const float*)d_in[1];   // hist_ent_emb
    const float* rel       = (const float*)d_in[2];   // hist_rel_emb
    const int*   htime     = (const int*)d_in[3];
    const int*   qtime     = (const int*)d_in[4];
    const void*  maskp     = (const void*)d_in[5];
    const float* W_rel     = (const float*)d_in[6];
    const float* W_q       = (const float*)d_in[7];
    const float* log_gamma = (const float*)d_in[8];
    const float* W1        = (const float*)d_in[9];
    const float* b1        = (const float*)d_in[10];
    const float* ln1_g     = (const float*)d_in[11];
    const float* ln1_b     = (const float*)d_in[12];
    const float* W2        = (const float*)d_in[13];
    const float* b2        = (const float*)d_in[14];
    const float* ln2_g     = (const float*)d_in[15];
    const float* ln2_b     = (const float*)d_in[16];
    const float* Wc        = (const float*)d_in[17];
    const float* bc        = (const float*)d_in[18];
    const float* lnc_g     = (const float*)d_in[19];
    const float* lnc_b     = (const float*)d_in[20];
    float* out = (float*)d_out;

    static int configured = 0;
    if (!configured) {
        cudaFuncSetAttribute(aggregate_kernel,
                             cudaFuncAttributeMaxDynamicSharedMemorySize,
                             H_SZ * E_SZ * (int)sizeof(float));
        cudaFuncSetAttribute(gemm_msgs_hmma,
                             cudaFuncAttributeMaxDynamicSharedMemorySize,
                             SM_HMMA);
        configured = 1;
    }

    // split W_rel into bf16 hi/lo (tiny)
    __nv_bfloat16 *p_w_hi, *p_w_lo;
    cudaGetSymbolAddress((void**)&p_w_hi, g_w_hi);
    cudaGetSymbolAddress((void**)&p_w_lo, g_w_lo);
    conv_split_kernel<<<64, 256>>>(W_rel, p_w_hi, p_w_lo,
                                   (size_t)E_SZ * R_SZ / 4);

    qrepr_kernel<<<B_SZ, 256>>>(e_emb, W_q);

    gemm_msgs_hmma<<<(B_SZ * H_SZ) / 128, 512, SM_HMMA>>>(rel, ent);

    aggregate_kernel<<<B_SZ, 256, H_SZ * E_SZ * (int)sizeof(float)>>>(
        e_emb, htime, qtime, maskp, log_gamma);

    mlp1_kernel<<<B_SZ, 512>>>(W1, b1, ln1_g, ln1_b);
    mlp2_kernel<<<B_SZ, 256>>>(W2, b2, ln2_g, ln2_b, out);
    ctx_kernel<<<B_SZ, 512>>>(Wc, bc, lnc_g, lnc_b, out);
}

// round 7
// speedup vs baseline: 2.4323x; 1.4554x over previous
#include <cuda_runtime.h>
#include <cuda_bf16.h>
#include <math.h>
#include <stdint.h>

#define B_SZ   1024
#define H_SZ   200
#define E_SZ   256
#define R_SZ   256
#define HID_SZ 512
#define LN_EPS 1e-5f

// -------------------- scratch (device globals) -----------------------------
__device__ float g_msgs[(size_t)B_SZ * H_SZ * E_SZ];
__device__ float g_logits[B_SZ * H_SZ];
__device__ float g_qrepr[B_SZ * E_SZ];
__device__ float g_combined[B_SZ * 4 * E_SZ];
__device__ float g_h1[B_SZ * 2 * E_SZ];
__device__ float g_lin1[B_SZ * HID_SZ];
__device__ float g_lin2[B_SZ * E_SZ];
__device__ __nv_bfloat16 g_w_hi[E_SZ * R_SZ];
__device__ __nv_bfloat16 g_w_lo[E_SZ * R_SZ];

// -------------------- helpers ----------------------------------------------
__device__ __forceinline__ uint32_t smem_to_u32(const void* p) {
    uint32_t a;
    asm("{ .reg .u64 t; cvta.to.shared.u64 t, %1; cvt.u32.u64 %0, t; }"
        : "=r"(a) : "l"(p));
    return a;
}
#define SMEM_SWIZZLE_128B(o) ((o) ^ (((o) >> 3) & 0x70))

#define LDSM_X4(r, a) \
    asm volatile("ldmatrix.sync.aligned.m8n8.x4.shared.b16 {%0,%1,%2,%3}, [%4];" \
                 : "=r"((r)[0]), "=r"((r)[1]), "=r"((r)[2]), "=r"((r)[3]) \
                 : "r"(a))

#define MMA_BF16(c, a, b0, b1) \
    asm volatile("mma.sync.aligned.m16n8k16.row.col.f32.bf16.bf16.f32 " \
                 "{%0,%1,%2,%3}, {%4,%5,%6,%7}, {%8,%9}, {%0,%1,%2,%3};" \
                 : "+f"((c)[0]), "+f"((c)[1]), "+f"((c)[2]), "+f"((c)[3]) \
                 : "r"((a)[0]), "r"((a)[1]), "r"((a)[2]), "r"((a)[3]), \
                   "r"(b0), "r"(b1))

__device__ __forceinline__ float warpReduceSum(float v) {
#pragma unroll
    for (int o = 16; o; o >>= 1) v += __shfl_xor_sync(0xffffffffu, v, o);
    return v;
}
__device__ __forceinline__ float warpReduceMax(float v) {
#pragma unroll
    for (int o = 16; o; o >>= 1) v = fmaxf(v, __shfl_xor_sync(0xffffffffu, v, o));
    return v;
}
__device__ __forceinline__ float gelu_exact(float x) {
    return 0.5f * x * (1.0f + erff(x * 0.70710678118654752f));
}
__device__ __forceinline__ int detect_mask_mode(const void* m) {
    const unsigned char* u = (const unsigned char*)m;
    const float* f = (const float*)m;
    bool is_i = true, is_f = true;
#pragma unroll
    for (int i = 0; i < 16; i++) {
        if (u[4 * i + 1] | u[4 * i + 2] | u[4 * i + 3]) is_i = false;
        float v = f[i];
        if (v != 0.0f && v != 1.0f) is_f = false;
    }
    if (is_i) return 1;
    if (is_f) return 2;
    return 0;
}
__device__ __forceinline__ float mask_val(const void* m, int idx, int mode) {
    if (mode == 1) return ((const int*)m)[idx] != 0 ? 1.f : 0.f;
    if (mode == 2) return ((const float*)m)[idx] != 0.f ? 1.f : 0.f;
    return ((const unsigned char*)m)[idx] ? 1.f : 0.f;
}
__device__ __forceinline__ unsigned pack_bf2(__nv_bfloat16 a, __nv_bfloat16 b) {
    __nv_bfloat162 t(a, b);
    return *reinterpret_cast<unsigned*>(&t);
}

// ===========================================================================
// Kernel 0: fp32 -> bf16 hi/lo split (W_rel only)
// ===========================================================================
__global__ void __launch_bounds__(256) conv_split_kernel(const float* __restrict__ src,
                                                         __nv_bfloat16* __restrict__ hi,
                                                         __nv_bfloat16* __restrict__ lo,
                                                         size_t n4) {
    size_t i = (size_t)blockIdx.x * 256 + threadIdx.x;
    const size_t stride = (size_t)gridDim.x * 256;
    for (; i < n4; i += stride) {
        float4 x = ((const float4*)src)[i];
        __nv_bfloat16 h0 = __float2bfloat16(x.x);
        __nv_bfloat16 h1 = __float2bfloat16(x.y);
        __nv_bfloat16 h2 = __float2bfloat16(x.z);
        __nv_bfloat16 h3 = __float2bfloat16(x.w);
        __nv_bfloat16 l0 = __float2bfloat16(x.x - __bfloat162float(h0));
        __nv_bfloat16 l1 = __float2bfloat16(x.y - __bfloat162float(h1));
        __nv_bfloat16 l2 = __float2bfloat16(x.z - __bfloat162float(h2));
        __nv_bfloat16 l3 = __float2bfloat16(x.w - __bfloat162float(h3));
        ((uint2*)hi)[i] = make_uint2(pack_bf2(h0, h1), pack_bf2(h2, h3));
        ((uint2*)lo)[i] = make_uint2(pack_bf2(l0, l1), pack_bf2(l2, l3));
    }
}

// ===========================================================================
// Generic fp32 tiled GEMM: C[M,N] = A[M,K] @ W[N,K]^T (+bias)
// BM=BN=64, BK=32, 256 threads, 4x4 micro-tile. M,N,K multiples of 64/64/32.
// ===========================================================================
__global__ void __launch_bounds__(256) gemm64_f32(const float* __restrict__ A,
                                                  const float* __restrict__ W,
                                                  const float* __restrict__ bias,
                                                  float* __restrict__ C,
                                                  int M, int N, int K) {
    __shared__ float As[32][68];
    __shared__ float Ws[32][68];
    const int tid = threadIdx.x;
    const int m0 = blockIdx.y * 64, n0 = blockIdx.x * 64;
    const int ty = tid >> 4, tx = tid & 15;
    float c[4][4] = {};
    for (int k0 = 0; k0 < K; k0 += 32) {
#pragma unroll
        for (int i = 0; i < 2; i++) {
            const int idx = tid + i * 256;
            const int row = idx >> 3, c4 = idx & 7;
            float4 a = *(const float4*)(A + (size_t)(m0 + row) * K + k0 + c4 * 4);
            As[c4 * 4 + 0][row] = a.x; As[c4 * 4 + 1][row] = a.y;
            As[c4 * 4 + 2][row] = a.z; As[c4 * 4 + 3][row] = a.w;
            float4 w = *(const float4*)(W + (size_t)(n0 + row) * K + k0 + c4 * 4);
            Ws[c4 * 4 + 0][row] = w.x; Ws[c4 * 4 + 1][row] = w.y;
            Ws[c4 * 4 + 2][row] = w.z; Ws[c4 * 4 + 3][row] = w.w;
        }
        __syncthreads();
#pragma unroll
        for (int k = 0; k < 32; k++) {
            float4 af = *(const float4*)&As[k][ty * 4];
            float4 wf = *(const float4*)&Ws[k][tx * 4];
            const float aa[4] = {af.x, af.y, af.z, af.w};
            const float ww[4] = {wf.x, wf.y, wf.z, wf.w};
#pragma unroll
            for (int i = 0; i < 4; i++)
#pragma unroll
                for (int j = 0; j < 4; j++) c[i][j] += aa[i] * ww[j];
        }
        __syncthreads();
    }
    float4 bv = bias ? *(const float4*)(bias + n0 + tx * 4) : make_float4(0.f, 0.f, 0.f, 0.f);
#pragma unroll
    for (int i = 0; i < 4; i++) {
        const int rm = m0 + ty * 4 + i;
        float4 o = make_float4(c[i][0] + bv.x, c[i][1] + bv.y,
                               c[i][2] + bv.z, c[i][3] + bv.w);
        *(float4*)(C + (size_t)rm * N + n0 + tx * 4) = o;
    }
}

// ===========================================================================
// LayerNorm (+ optional exact GELU), one row per block, blockDim == N
// ===========================================================================
__global__ void ln_act_kernel(const float* __restrict__ src, const float* __restrict__ gg,
                              const float* __restrict__ bb, float* __restrict__ dst,
                              int N, int do_gelu) {
    __shared__ float s_red[16];
    __shared__ float s_b;
    const int b = blockIdx.x, tid = threadIdx.x;
    const int wid = tid >> 5, lane = tid & 31;
    const int nw = blockDim.x >> 5;
    float x = src[(size_t)b * N + tid];
    float s = warpReduceSum(x);
    if (lane == 0) s_red[wid] = s;
    __syncthreads();
    if (tid < 32) {
        float t = (lane < nw) ? s_red[lane] : 0.f;
        t = warpReduceSum(t);
        if (lane == 0) s_b = t;
    }
    __syncthreads();
    const float mu = s_b / N;
    const float d = x - mu;
    float s2 = warpReduceSum(d * d);
    if (lane == 0) s_red[wid] = s2;
    __syncthreads();
    if (tid < 32) {
        float t = (lane < nw) ? s_red[lane] : 0.f;
        t = warpReduceSum(t);
        if (lane == 0) s_b = t;
    }
    __syncthreads();
    const float var = s_b / N;
    float y = d * rsqrtf(var + LN_EPS) * gg[tid] + bb[tid];
    dst[(size_t)b * N + tid] = do_gelu ? gelu_exact(y) : y;
}

// ===========================================================================
// Kernel B (HMMA): messages + fused attention logits.
// CTA = 128(M) x 256(N=full E), BK=64, 512 threads (16 warps, 4m x 4n).
// Epilogue: msgs = acc*ent -> gmem; logit[row] = dot(q_repr[b(row)], msgs_row)
// via smem atomics -> g_logits.
// ===========================================================================
#define O_AH 0
#define O_AL 16384
#define O_BH 32768
#define O_BL 65536
#define SM_HMMA 98304

__global__ void __launch_bounds__(512, 1) gemm_msgs_hmma(const float* __restrict__ rel,
                                                         const float* __restrict__ ent) {
    extern __shared__ char sm[];
    const uint32_t smb = smem_to_u32(sm);
    const int tid = threadIdx.x;
    const int warp = tid >> 5, lane = tid & 31;
    const int wm = warp & 3, wn = warp >> 2;
    const int m0 = blockIdx.x * 128;

    float acc[2][8][4];
#pragma unroll
    for (int i = 0; i < 2; i++)
#pragma unroll
        for (int j = 0; j < 8; j++)
#pragma unroll
            for (int q = 0; q < 4; q++) acc[i][j][q] = 0.f;

    const char* whp = (const char*)g_w_hi;
    const char* wlp = (const char*)g_w_lo;

    for (int s = 0; s < 4; s++) {
        const float* asrc = rel + (size_t)m0 * R_SZ + s * 64;
#pragma unroll
        for (int j = 0; j < 4; j++) {
            const int idx = tid + j * 512;
            const int row = idx >> 4, c4 = idx & 15;
            float4 x = *(const float4*)(asrc + (size_t)row * R_SZ + c4 * 4);
            __nv_bfloat16 h0 = __float2bfloat16(x.x);
            __nv_bfloat16 h1 = __float2bfloat16(x.y);
            __nv_bfloat16 h2 = __float2bfloat16(x.z);
            __nv_bfloat16 h3 = __float2bfloat16(x.w);
            __nv_bfloat16 l0 = __float2bfloat16(x.x - __bfloat162float(h0));
            __nv_bfloat16 l1 = __float2bfloat16(x.y - __bfloat162float(h1));
            __nv_bfloat16 l2 = __float2bfloat16(x.z - __bfloat162float(h2));
            __nv_bfloat16 l3 = __float2bfloat16(x.w - __bfloat162float(h3));
            const int bo = SMEM_SWIZZLE_128B(row * 128 + c4 * 8);
            *(uint2*)(sm + O_AH + bo) = make_uint2(pack_bf2(h0, h1), pack_bf2(h2, h3));
            *(uint2*)(sm + O_AL + bo) = make_uint2(pack_bf2(l0, l1), pack_bf2(l2, l3));
        }
        const size_t bsrc = (size_t)s * 128;
#pragma unroll
        for (int j = 0; j < 4; j++) {
            const int idx = tid + j * 512;
            const int row = idx >> 3, ch = idx & 7;
            const size_t so = bsrc + (size_t)row * 512 + ch * 16;
            const int bo = SMEM_SWIZZLE_128B(row * 128 + ch * 16);
            *(uint4*)(sm + O_BH + bo) = *(const uint4*)(whp + so);
            *(uint4*)(sm + O_BL + bo) = *(const uint4*)(wlp + so);
        }
        __syncthreads();

#pragma unroll
        for (int kk = 0; kk < 4; kk++) {
            uint32_t ah[2][4], al[2][4];
#pragma unroll
            for (int mt = 0; mt < 2; mt++) {
                const int arow = wm * 32 + mt * 16 + (lane & 15);
                const int aoff = SMEM_SWIZZLE_128B(arow * 128 + kk * 32 + ((lane >> 4) & 1) * 16);
                LDSM_X4(ah[mt], smb + O_AH + aoff);
                LDSM_X4(al[mt], smb + O_AL + aoff);
            }
#pragma unroll
            for (int np = 0; np < 4; np++) {
                const int nrow = wn * 64 + np * 16 + (lane & 7) + ((lane >> 4) & 1) * 8;
                const int boff = SMEM_SWIZZLE_128B(nrow * 128 + kk * 32 + ((lane >> 3) & 1) * 16);
                uint32_t bh4[4], bl4[4];
                LDSM_X4(bh4, smb + O_BH + boff);
                LDSM_X4(bl4, smb + O_BL + boff);
#pragma unroll
                for (int mt = 0; mt < 2; mt++) {
#pragma unroll
                    for (int h = 0; h < 2; h++) {
                        float* c = acc[mt][np * 2 + h];
                        MMA_BF16(c, ah[mt], bh4[2 * h], bh4[2 * h + 1]);
                        MMA_BF16(c, ah[mt], bl4[2 * h], bl4[2 * h + 1]);
                        MMA_BF16(c, al[mt], bh4[2 * h], bh4[2 * h + 1]);
                    }
                }
            }
        }
        __syncthreads();
    }

    // ---- logits staging (alias A-tile smem; k-loop done) -------------------
    float* s_logit = (float*)sm;               // 128 floats
    float* s_qv    = (float*)(sm + 512);       // 2 x 256 floats
    if (tid < 128) s_logit[tid] = 0.f;
    const int bA = m0 / H_SZ;
    const int bB = (m0 + 127) / H_SZ;
    {
        const int part = tid >> 8, col = tid & 255;
        const int qb = part ? bB : bA;
        s_qv[tid] = g_qrepr[qb * E_SZ + col];
    }
    __syncthreads();

    // ---- epilogue: msgs = acc*ent; accumulate per-row q-dot ----------------
    const int g = lane >> 2, tig = lane & 3;
#pragma unroll
    for (int mt = 0; mt < 2; mt++) {
        const int lr0 = wm * 32 + mt * 16 + g;
        const int lr1 = lr0 + 8;
        const float* q0 = s_qv + (((m0 + lr0) / H_SZ == bA) ? 0 : 256);
        const float* q1 = s_qv + (((m0 + lr1) / H_SZ == bA) ? 0 : 256);
        float p0 = 0.f, p1 = 0.f;
#pragma unroll
        for (int nt = 0; nt < 8; nt++) {
            const int c = wn * 64 + nt * 8 + tig * 2;
            const size_t o1 = (size_t)(m0 + lr0) * E_SZ + c;
            const size_t o2 = (size_t)(m0 + lr1) * E_SZ + c;
            float2 e1 = *(const float2*)(ent + o1);
            float2 e2 = *(const float2*)(ent + o2);
            const float v00 = acc[mt][nt][0] * e1.x, v01 = acc[mt][nt][1] * e1.y;
            const float v10 = acc[mt][nt][2] * e2.x, v11 = acc[mt][nt][3] * e2.y;
            *(float2*)(g_msgs + o1) = make_float2(v00, v01);
            *(float2*)(g_msgs + o2) = make_float2(v10, v11);
            p0 += v00 * q0[c] + v01 * q0[c + 1];
            p1 += v10 * q1[c] + v11 * q1[c + 1];
        }
        atomicAdd(&s_logit[lr0], p0);
        atomicAdd(&s_logit[lr1], p1);
    }
    __syncthreads();
    if (tid < 128) g_logits[m0 + tid] = s_logit[tid];
}

// ===========================================================================
// Kernel C (v2): softmax from precomputed logits + streaming PNA reductions.
// No big smem -> high occupancy; single coalesced pass over g_msgs.
// ===========================================================================
__global__ void __launch_bounds__(256) aggregate_v2(const float* __restrict__ e_emb,
                                                    const int* __restrict__ htime,
                                                    const int* __restrict__ qtime,
                                                    const void* __restrict__ maskp,
                                                    const float* __restrict__ log_gamma) {
    __shared__ float s_w[H_SZ];
    __shared__ float s_mask[H_SZ];
    __shared__ float s_red[8];
    __shared__ float s_b0, s_b1, s_b2;
    __shared__ int s_mode;

    const int b = blockIdx.x, tid = threadIdx.x;
    const int wid = tid >> 5, lane = tid & 31;

    if (tid == 0) s_mode = detect_mask_mode(maskp);
    __syncthreads();

    float lg = -INFINITY, mk = 0.f;
    if (tid < H_SZ) {
        mk = mask_val(maskp, b * H_SZ + tid, s_mode);
        s_mask[tid] = mk;
        float raw = g_logits[b * H_SZ + tid];
        float td = fmaxf((float)qtime[b] - (float)htime[b * H_SZ + tid], 0.f);
        float dec = expf(-expf(log_gamma[0]) * td);
        lg = (mk != 0.f) ? raw * dec * 0.0625f : -1e9f;
    }
    // block max
    {
        float m = warpReduceMax(lg);
        if (lane == 0) s_red[wid] = m;
        __syncthreads();
        if (tid < 32) {
            float t = (lane < 8) ? s_red[lane] : -INFINITY;
            t = warpReduceMax(t);
            if (lane == 0) s_b0 = t;
        }
        __syncthreads();
    }
    const float mx = s_b0;
    float ex = (tid < H_SZ) ? expf(lg - mx) : 0.f;
    {
        float ss = warpReduceSum(ex);
        if (lane == 0) s_red[wid] = ss;
        __syncthreads();
        if (tid < 32) {
            float t = (lane < 8) ? s_red[lane] : 0.f;
            t = warpReduceSum(t);
            if (lane == 0) s_b1 = t;
        }
        __syncthreads();
        float cc = warpReduceSum(mk);
        if (lane == 0) s_red[wid] = cc;
        __syncthreads();
        if (tid < 32) {
            float t = (lane < 8) ? s_red[lane] : 0.f;
            t = warpReduceSum(t);
            if (lane == 0) s_b2 = t;
        }
        __syncthreads();
    }
    if (tid < H_SZ) s_w[tid] = ex / s_b1;
    __syncthreads();

    // streaming reductions: thread = e channel, coalesced across warp
    const float* base = g_msgs + (size_t)b * H_SZ * E_SZ + tid;
    float mean = 0.f, mxv = -INFINITY, am = 0.f;
#pragma unroll 8
    for (int h = 0; h < H_SZ; h++) {
        float val = base[(size_t)h * E_SZ];
        float m = s_mask[h];
        float vm = val * m;
        mean += vm;
        mxv = fmaxf(mxv, vm);
        am += val * s_w[h];
    }
    const float nv = fmaxf(s_b2, 1.f);
    float* outr = g_combined + (size_t)b * 4 * E_SZ;
    outr[tid]            = mean / nv;
    outr[E_SZ + tid]     = mxv;
    outr[2 * E_SZ + tid] = am;
    outr[3 * E_SZ + tid] = e_emb[b * E_SZ + tid];
}

// ===========================================================================
extern "C" void kernel_launch(void* const* d_in, const int* in_sizes, int n_in,
                              void* d_out, int out_size) {
    const float* e_emb     = (const float*)d_in[0];
    const float* ent       = (const float*)d_in[1];
    const float* rel       = (const float*)d_in[2];
    const int*   htime     = (const int*)d_in[3];
    const int*   qtime     = (const int*)d_in[4];
    const void*  maskp     = (const void*)d_in[5];
    const float* W_rel     = (const float*)d_in[6];
    const float* W_q       = (const float*)d_in[7];
    const float* log_gamma = (const float*)d_in[8];
    const float* W1        = (const float*)d_in[9];
    const float* b1        = (const float*)d_in[10];
    const float* ln1_g     = (const float*)d_in[11];
    const float* ln1_b     = (const float*)d_in[12];
    const float* W2        = (const float*)d_in[13];
    const float* b2        = (const float*)d_in[14];
    const float* ln2_g     = (const float*)d_in[15];
    const float* ln2_b     = (const float*)d_in[16];
    const float* Wc        = (const float*)d_in[17];
    const float* bc        = (const float*)d_in[18];
    const float* lnc_g     = (const float*)d_in[19];
    const float* lnc_b     = (const float*)d_in[20];
    float* out = (float*)d_out;

    static int configured = 0;
    if (!configured) {
        cudaFuncSetAttribute(gemm_msgs_hmma,
                             cudaFuncAttributeMaxDynamicSharedMemorySize,
                             SM_HMMA);
        configured = 1;
    }

    __nv_bfloat16 *p_w_hi, *p_w_lo;
    cudaGetSymbolAddress((void**)&p_w_hi, g_w_hi);
    cudaGetSymbolAddress((void**)&p_w_lo, g_w_lo);
    float *p_qrepr, *p_comb, *p_h1, *p_lin1, *p_lin2;
    cudaGetSymbolAddress((void**)&p_qrepr, g_qrepr);
    cudaGetSymbolAddress((void**)&p_comb, g_combined);
    cudaGetSymbolAddress((void**)&p_h1, g_h1);
    cudaGetSymbolAddress((void**)&p_lin1, g_lin1);
    cudaGetSymbolAddress((void**)&p_lin2, g_lin2);

    conv_split_kernel<<<64, 256>>>(W_rel, p_w_hi, p_w_lo,
                                   (size_t)E_SZ * R_SZ / 4);

    // q_repr = e_emb @ W_q^T  (M=1024, N=256, K=256)
    gemm64_f32<<<dim3(E_SZ / 64, B_SZ / 64), 256>>>(e_emb, W_q, nullptr, p_qrepr,
                                                    B_SZ, E_SZ, E_SZ);

    gemm_msgs_hmma<<<(B_SZ * H_SZ) / 128, 512, SM_HMMA>>>(rel, ent);

    aggregate_v2<<<B_SZ, 256>>>(e_emb, htime, qtime, maskp, log_gamma);

    // MLP1: lin1 = combined @ W1^T + b1 ; h1 = gelu(LN(lin1))
    gemm64_f32<<<dim3(HID_SZ / 64, B_SZ / 64), 256>>>(p_comb, W1, b1, p_lin1,
                                                      B_SZ, HID_SZ, 4 * E_SZ);
    ln_act_kernel<<<B_SZ, HID_SZ>>>(p_lin1, ln1_g, ln1_b, p_h1, HID_SZ, 1);

    // MLP2: lin2 = h1 @ W2^T + b2 ; dyn = LN(lin2) -> out[0 .. B*E)
    gemm64_f32<<<dim3(E_SZ / 64, B_SZ / 64), 256>>>(p_h1, W2, b2, p_lin2,
                                                    B_SZ, E_SZ, HID_SZ);
    ln_act_kernel<<<B_SZ, E_SZ>>>(p_lin2, ln2_g, ln2_b, out, E_SZ, 0);

    // CTX: lin1 = dyn @ Wc^T + bc ; ctx = gelu(LN(lin1)) -> out[B*E ..)
    gemm64_f32<<<dim3(HID_SZ / 64, B_SZ / 64), 256>>>(out, Wc, bc, p_lin1,
                                                      B_SZ, HID_SZ, E_SZ);
    ln_act_kernel<<<B_SZ, HID_SZ>>>(p_lin1, lnc_g, lnc_b,
                                    out + (size_t)B_SZ * E_SZ, HID_SZ, 1);
}

// round 9
// speedup vs baseline: 3.4211x; 1.4065x over previous
#include <cuda_runtime.h>
#include <cuda_fp16.h>
#include <math.h>
#include <stdint.h>

#define B_SZ   1024
#define H_SZ   200
#define E_SZ   256
#define R_SZ   256
#define HID_SZ 512
#define LN_EPS 1e-5f

// -------------------- scratch (device globals) -----------------------------
__device__ float g_msgs[(size_t)B_SZ * H_SZ * E_SZ];
__device__ float g_logits[B_SZ * H_SZ];
__device__ float g_qrepr[B_SZ * E_SZ];
__device__ float g_combined[B_SZ * 4 * E_SZ];
__device__ float g_h1[B_SZ * 2 * E_SZ];
__device__ float g_lin1[B_SZ * HID_SZ];
__device__ float g_lin2[B_SZ * E_SZ];
__device__ __half g_wrel_h[E_SZ * R_SZ];
__device__ __half g_wq_h[E_SZ * E_SZ];
__device__ __half g_w1_h[(2 * E_SZ) * (4 * E_SZ)];
__device__ __half g_w2_h[E_SZ * (2 * E_SZ)];
__device__ __half g_wc_h[HID_SZ * E_SZ];

// -------------------- helpers ----------------------------------------------
__device__ __forceinline__ uint32_t smem_to_u32(const void* p) {
    uint32_t a;
    asm("{ .reg .u64 t; cvta.to.shared.u64 t, %1; cvt.u32.u64 %0, t; }"
        : "=r"(a) : "l"(p));
    return a;
}
#define SMEM_SWIZZLE_128B(o) ((o) ^ (((o) >> 3) & 0x70))

#define LDSM_X4(r, a) \
    asm volatile("ldmatrix.sync.aligned.m8n8.x4.shared.b16 {%0,%1,%2,%3}, [%4];" \
                 : "=r"((r)[0]), "=r"((r)[1]), "=r"((r)[2]), "=r"((r)[3]) \
                 : "r"(a))

#define MMA_F16(c, a, b0, b1) \
    asm volatile("mma.sync.aligned.m16n8k16.row.col.f32.f16.f16.f32 " \
                 "{%0,%1,%2,%3}, {%4,%5,%6,%7}, {%8,%9}, {%0,%1,%2,%3};" \
                 : "+f"((c)[0]), "+f"((c)[1]), "+f"((c)[2]), "+f"((c)[3]) \
                 : "r"((a)[0]), "r"((a)[1]), "r"((a)[2]), "r"((a)[3]), \
                   "r"(b0), "r"(b1))

__device__ __forceinline__ float warpReduceSum(float v) {
#pragma unroll
    for (int o = 16; o; o >>= 1) v += __shfl_xor_sync(0xffffffffu, v, o);
    return v;
}
__device__ __forceinline__ float warpReduceMax(float v) {
#pragma unroll
    for (int o = 16; o; o >>= 1) v = fmaxf(v, __shfl_xor_sync(0xffffffffu, v, o));
    return v;
}
__device__ __forceinline__ float gelu_exact(float x) {
    return 0.5f * x * (1.0f + erff(x * 0.70710678118654752f));
}
__device__ __forceinline__ int detect_mask_mode(const void* m) {
    const unsigned char* u = (const unsigned char*)m;
    const float* f = (const float*)m;
    bool is_i = true, is_f = true;
#pragma unroll
    for (int i = 0; i < 16; i++) {
        if (u[4 * i + 1] | u[4 * i + 2] | u[4 * i + 3]) is_i = false;
        float v = f[i];
        if (v != 0.0f && v != 1.0f) is_f = false;
    }
    if (is_i) return 1;
    if (is_f) return 2;
    return 0;
}
__device__ __forceinline__ float mask_val(const void* m, int idx, int mode) {
    if (mode == 1) return ((const int*)m)[idx] != 0 ? 1.f : 0.f;
    if (mode == 2) return ((const float*)m)[idx] != 0.f ? 1.f : 0.f;
    return ((const unsigned char*)m)[idx] ? 1.f : 0.f;
}
__device__ __forceinline__ uint32_t pack_hf2(float a, float b) {
    __half2 t = __floats2half2_rn(a, b);
    return *reinterpret_cast<uint32_t*>(&t);
}

// ===========================================================================
// Kernel 0: fp32 -> fp16 convert (weights)
// ===========================================================================
__global__ void __launch_bounds__(256) conv_fp16_kernel(const float* __restrict__ src,
                                                        __half* __restrict__ dst,
                                                        size_t n4) {
    size_t i = (size_t)blockIdx.x * 256 + threadIdx.x;
    const size_t stride = (size_t)gridDim.x * 256;
    for (; i < n4; i += stride) {
        float4 x = ((const float4*)src)[i];
        ((uint2*)dst)[i] = make_uint2(pack_hf2(x.x, x.y), pack_hf2(x.z, x.w));
    }
}

// ===========================================================================
// Generic HMMA linear: C[M,N] = A_f32[M,K] @ W_f16[N,K]^T (+bias)
// CTA 128(M) x 64(N), 256 thr (8 warps 4m x 2n), warp tile 32x32, BK=64.
// A fp32->fp16 conversion fused into the tile loader.
// ===========================================================================
#define HL_OA 0
#define HL_OB 16384
__global__ void __launch_bounds__(256) hmma_linear(const float* __restrict__ A,
                                                   const __half* __restrict__ W,
                                                   const float* __restrict__ bias,
                                                   float* __restrict__ C,
                                                   int M, int N, int K) {
    __shared__ char sm[16384 + 8192];
    const uint32_t smb = smem_to_u32(sm);
    const int tid = threadIdx.x;
    const int warp = tid >> 5, lane = tid & 31;
    const int wm = warp & 3, wn = warp >> 2;
    const int m0 = blockIdx.y * 128, n0 = blockIdx.x * 64;

    float acc[2][4][4];
#pragma unroll
    for (int i = 0; i < 2; i++)
#pragma unroll
        for (int j = 0; j < 4; j++)
#pragma unroll
            for (int q = 0; q < 4; q++) acc[i][j][q] = 0.f;

    for (int k0 = 0; k0 < K; k0 += 64) {
        // A tile: 128 x 64 fp32 -> fp16 (SW128, 128B rows)
        const float* asrc = A + (size_t)m0 * K + k0;
#pragma unroll
        for (int j = 0; j < 8; j++) {
            const int idx = tid + j * 256;
            const int row = idx >> 4, c4 = idx & 15;
            float4 x = *(const float4*)(asrc + (size_t)row * K + c4 * 4);
            const int bo = SMEM_SWIZZLE_128B(row * 128 + c4 * 8);
            *(uint2*)(sm + HL_OA + bo) = make_uint2(pack_hf2(x.x, x.y), pack_hf2(x.z, x.w));
        }
        // B tile: 64 x 64 fp16 from pre-converted W
        const __half* bsrc = W + (size_t)n0 * K + k0;
#pragma unroll
        for (int j = 0; j < 2; j++) {
            const int idx = tid + j * 256;
            const int row = idx >> 3, ch = idx & 7;
            const int bo = SMEM_SWIZZLE_128B(row * 128 + ch * 16);
            *(uint4*)(sm + HL_OB + bo) = *(const uint4*)(bsrc + (size_t)row * K + ch * 8);
        }
        __syncthreads();

#pragma unroll
        for (int kk = 0; kk < 4; kk++) {
            uint32_t ah[2][4];
#pragma unroll
            for (int mt = 0; mt < 2; mt++) {
                const int arow = wm * 32 + mt * 16 + (lane & 15);
                const int aoff = SMEM_SWIZZLE_128B(arow * 128 + kk * 32 + ((lane >> 4) & 1) * 16);
                LDSM_X4(ah[mt], smb + HL_OA + aoff);
            }
#pragma unroll
            for (int np = 0; np < 2; np++) {
                const int nrow = wn * 32 + np * 16 + (lane & 7) + ((lane >> 4) & 1) * 8;
                const int boff = SMEM_SWIZZLE_128B(nrow * 128 + kk * 32 + ((lane >> 3) & 1) * 16);
                uint32_t b4[4];
                LDSM_X4(b4, smb + HL_OB + boff);
#pragma unroll
                for (int mt = 0; mt < 2; mt++) {
#pragma unroll
                    for (int h = 0; h < 2; h++)
                        MMA_F16(acc[mt][np * 2 + h], ah[mt], b4[2 * h], b4[2 * h + 1]);
                }
            }
        }
        __syncthreads();
    }

    const int g = lane >> 2, tig = lane & 3;
#pragma unroll
    for (int mt = 0; mt < 2; mt++) {
        const int r0 = m0 + wm * 32 + mt * 16 + g;
        const int r1 = r0 + 8;
#pragma unroll
        for (int j = 0; j < 4; j++) {
            const int col = n0 + wn * 32 + j * 8 + tig * 2;
            float bx = 0.f, by = 0.f;
            if (bias) { bx = bias[col]; by = bias[col + 1]; }
            *(float2*)(C + (size_t)r0 * N + col) =
                make_float2(acc[mt][j][0] + bx, acc[mt][j][1] + by);
            *(float2*)(C + (size_t)r1 * N + col) =
                make_float2(acc[mt][j][2] + bx, acc[mt][j][3] + by);
        }
    }
}

// ===========================================================================
// LayerNorm (+ optional exact GELU), one row per block, blockDim == N
// ===========================================================================
__global__ void ln_act_kernel(const float* __restrict__ src, const float* __restrict__ gg,
                              const float* __restrict__ bb, float* __restrict__ dst,
                              int N, int do_gelu) {
    __shared__ float s_red[16];
    __shared__ float s_b;
    const int b = blockIdx.x, tid = threadIdx.x;
    const int wid = tid >> 5, lane = tid & 31;
    const int nw = blockDim.x >> 5;
    float x = src[(size_t)b * N + tid];
    float s = warpReduceSum(x);
    if (lane == 0) s_red[wid] = s;
    __syncthreads();
    if (tid < 32) {
        float t = (lane < nw) ? s_red[lane] : 0.f;
        t = warpReduceSum(t);
        if (lane == 0) s_b = t;
    }
    __syncthreads();
    const float mu = s_b / N;
    const float d = x - mu;
    float s2 = warpReduceSum(d * d);
    if (lane == 0) s_red[wid] = s2;
    __syncthreads();
    if (tid < 32) {
        float t = (lane < nw) ? s_red[lane] : 0.f;
        t = warpReduceSum(t);
        if (lane == 0) s_b = t;
    }
    __syncthreads();
    const float var = s_b / N;
    float y = d * rsqrtf(var + LN_EPS) * gg[tid] + bb[tid];
    dst[(size_t)b * N + tid] = do_gelu ? gelu_exact(y) : y;
}

// ===========================================================================
// Kernel B (HMMA fp16, single term): messages + fused attention logits.
// CTA = 128(M) x 256(N=full E), BK=64, 512 threads (16 warps 4m x 4n).
// ===========================================================================
#define O_A 0
#define O_B 16384
#define SM_HMMA 49152

__global__ void __launch_bounds__(512, 1) gemm_msgs_hmma(const float* __restrict__ rel,
                                                         const float* __restrict__ ent) {
    extern __shared__ char sm[];
    const uint32_t smb = smem_to_u32(sm);
    const int tid = threadIdx.x;
    const int warp = tid >> 5, lane = tid & 31;
    const int wm = warp & 3, wn = warp >> 2;
    const int m0 = blockIdx.x * 128;

    float acc[2][8][4];
#pragma unroll
    for (int i = 0; i < 2; i++)
#pragma unroll
        for (int j = 0; j < 8; j++)
#pragma unroll
            for (int q = 0; q < 4; q++) acc[i][j][q] = 0.f;

    const char* wp = (const char*)g_wrel_h;

    for (int s = 0; s < 4; s++) {
        // A tile: 128 rows x 64 fp32 -> fp16 (SW128)
        const float* asrc = rel + (size_t)m0 * R_SZ + s * 64;
#pragma unroll
        for (int j = 0; j < 4; j++) {
            const int idx = tid + j * 512;
            const int row = idx >> 4, c4 = idx & 15;
            float4 x = *(const float4*)(asrc + (size_t)row * R_SZ + c4 * 4);
            const int bo = SMEM_SWIZZLE_128B(row * 128 + c4 * 8);
            *(uint2*)(sm + O_A + bo) = make_uint2(pack_hf2(x.x, x.y), pack_hf2(x.z, x.w));
        }
        // B tile: 256 rows x 64 fp16 (pre-converted W_rel)
        const size_t bsrc = (size_t)s * 128;
#pragma unroll
        for (int j = 0; j < 4; j++) {
            const int idx = tid + j * 512;
            const int row = idx >> 3, ch = idx & 7;
            const size_t so = bsrc + (size_t)row * 512 + ch * 16;
            const int bo = SMEM_SWIZZLE_128B(row * 128 + ch * 16);
            *(uint4*)(sm + O_B + bo) = *(const uint4*)(wp + so);
        }
        __syncthreads();

#pragma unroll
        for (int kk = 0; kk < 4; kk++) {
            uint32_t ah[2][4];
#pragma unroll
            for (int mt = 0; mt < 2; mt++) {
                const int arow = wm * 32 + mt * 16 + (lane & 15);
                const int aoff = SMEM_SWIZZLE_128B(arow * 128 + kk * 32 + ((lane >> 4) & 1) * 16);
                LDSM_X4(ah[mt], smb + O_A + aoff);
            }
#pragma unroll
            for (int np = 0; np < 4; np++) {
                const int nrow = wn * 64 + np * 16 + (lane & 7) + ((lane >> 4) & 1) * 8;
                const int boff = SMEM_SWIZZLE_128B(nrow * 128 + kk * 32 + ((lane >> 3) & 1) * 16);
                uint32_t b4[4];
                LDSM_X4(b4, smb + O_B + boff);
#pragma unroll
                for (int mt = 0; mt < 2; mt++) {
#pragma unroll
                    for (int h = 0; h < 2; h++)
                        MMA_F16(acc[mt][np * 2 + h], ah[mt], b4[2 * h], b4[2 * h + 1]);
                }
            }
        }
        __syncthreads();
    }

    // ---- logits staging (alias A-tile smem) --------------------------------
    float* s_logit = (float*)sm;               // 128 floats
    float* s_qv    = (float*)(sm + 512);       // 2 x 256 floats
    if (tid < 128) s_logit[tid] = 0.f;
    const int bA = m0 / H_SZ;
    const int bB = (m0 + 127) / H_SZ;
    {
        const int part = tid >> 8, col = tid & 255;
        const int qb = part ? bB : bA;
        s_qv[tid] = g_qrepr[qb * E_SZ + col];
    }
    __syncthreads();

    // ---- epilogue: msgs = acc*ent; per-row q-dot via smem atomics ----------
    const int g = lane >> 2, tig = lane & 3;
#pragma unroll
    for (int mt = 0; mt < 2; mt++) {
        const int lr0 = wm * 32 + mt * 16 + g;
        const int lr1 = lr0 + 8;
        const float* q0 = s_qv + (((m0 + lr0) / H_SZ == bA) ? 0 : 256);
        const float* q1 = s_qv + (((m0 + lr1) / H_SZ == bA) ? 0 : 256);
        float p0 = 0.f, p1 = 0.f;
#pragma unroll
        for (int nt = 0; nt < 8; nt++) {
            const int c = wn * 64 + nt * 8 + tig * 2;
            const size_t o1 = (size_t)(m0 + lr0) * E_SZ + c;
            const size_t o2 = (size_t)(m0 + lr1) * E_SZ + c;
            float2 e1 = *(const float2*)(ent + o1);
            float2 e2 = *(const float2*)(ent + o2);
            const float v00 = acc[mt][nt][0] * e1.x, v01 = acc[mt][nt][1] * e1.y;
            const float v10 = acc[mt][nt][2] * e2.x, v11 = acc[mt][nt][3] * e2.y;
            *(float2*)(g_msgs + o1) = make_float2(v00, v01);
            *(float2*)(g_msgs + o2) = make_float2(v10, v11);
            p0 += v00 * q0[c] + v01 * q0[c + 1];
            p1 += v10 * q1[c] + v11 * q1[c + 1];
        }
        atomicAdd(&s_logit[lr0], p0);
        atomicAdd(&s_logit[lr1], p1);
    }
    __syncthreads();
    if (tid < 128) g_logits[m0 + tid] = s_logit[tid];
}

// ===========================================================================
// Kernel C: softmax from precomputed logits + streaming PNA reductions.
// ===========================================================================
__global__ void __launch_bounds__(256) aggregate_v2(const float* __restrict__ e_emb,
                                                    const int* __restrict__ htime,
                                                    const int* __restrict__ qtime,
                                                    const void* __restrict__ maskp,
                                                    const float* __restrict__ log_gamma) {
    __shared__ float s_w[H_SZ];
    __shared__ float s_mask[H_SZ];
    __shared__ float s_red[8];
    __shared__ float s_b0, s_b1, s_b2;
    __shared__ int s_mode;

    const int b = blockIdx.x, tid = threadIdx.x;
    const int wid = tid >> 5, lane = tid & 31;

    if (tid == 0) s_mode = detect_mask_mode(maskp);
    __syncthreads();

    float lg = -INFINITY, mk = 0.f;
    if (tid < H_SZ) {
        mk = mask_val(maskp, b * H_SZ + tid, s_mode);
        s_mask[tid] = mk;
        float raw = g_logits[b * H_SZ + tid];
        float td = fmaxf((float)qtime[b] - (float)htime[b * H_SZ + tid], 0.f);
        float dec = expf(-expf(log_gamma[0]) * td);
        lg = (mk != 0.f) ? raw * dec * 0.0625f : -1e9f;
    }
    {
        float m = warpReduceMax(lg);
        if (lane == 0) s_red[wid] = m;
        __syncthreads();
        if (tid < 32) {
            float t = (lane < 8) ? s_red[lane] : -INFINITY;
            t = warpReduceMax(t);
            if (lane == 0) s_b0 = t;
        }
        __syncthreads();
    }
    const float mx = s_b0;
    float ex = (tid < H_SZ) ? expf(lg - mx) : 0.f;
    {
        float ss = warpReduceSum(ex);
        if (lane == 0) s_red[wid] = ss;
        __syncthreads();
        if (tid < 32) {
            float t = (lane < 8) ? s_red[lane] : 0.f;
            t = warpReduceSum(t);
            if (lane == 0) s_b1 = t;
        }
        __syncthreads();
        float cc = warpReduceSum(mk);
        if (lane == 0) s_red[wid] = cc;
        __syncthreads();
        if (tid < 32) {
            float t = (lane < 8) ? s_red[lane] : 0.f;
            t = warpReduceSum(t);
            if (lane == 0) s_b2 = t;
        }
        __syncthreads();
    }
    if (tid < H_SZ) s_w[tid] = ex / s_b1;
    __syncthreads();

    const float* base = g_msgs + (size_t)b * H_SZ * E_SZ + tid;
    float mean = 0.f, mxv = -INFINITY, am = 0.f;
#pragma unroll 8
    for (int h = 0; h < H_SZ; h++) {
        float val = base[(size_t)h * E_SZ];
        float m = s_mask[h];
        float vm = val * m;
        mean += vm;
        mxv = fmaxf(mxv, vm);
        am += val * s_w[h];
    }
    const float nv = fmaxf(s_b2, 1.f);
    float* outr = g_combined + (size_t)b * 4 * E_SZ;
    outr[tid]            = mean / nv;
    outr[E_SZ + tid]     = mxv;
    outr[2 * E_SZ + tid] = am;
    outr[3 * E_SZ + tid] = e_emb[b * E_SZ + tid];
}

// ===========================================================================
extern "C" void kernel_launch(void* const* d_in, const int* in_sizes, int n_in,
                              void* d_out, int out_size) {
    const float* e_emb     = (const float*)d_in[0];
    const float* ent       = (const float*)d_in[1];
    const float* rel       = (const float*)d_in[2];
    const int*   htime     = (const int*)d_in[3];
    const int*   qtime     = (const int*)d_in[4];
    const void*  maskp     = (const void*)d_in[5];
    const float* W_rel     = (const float*)d_in[6];
    const float* W_q       = (const float*)d_in[7];
    const float* log_gamma = (const float*)d_in[8];
    const float* W1        = (const float*)d_in[9];
    const float* b1        = (const float*)d_in[10];
    const float* ln1_g     = (const float*)d_in[11];
    const float* ln1_b     = (const float*)d_in[12];
    const float* W2        = (const float*)d_in[13];
    const float* b2        = (const float*)d_in[14];
    const float* ln2_g     = (const float*)d_in[15];
    const float* ln2_b     = (const float*)d_in[16];
    const float* Wc        = (const float*)d_in[17];
    const float* bc        = (const float*)d_in[18];
    const float* lnc_g     = (const float*)d_in[19];
    const float* lnc_b     = (const float*)d_in[20];
    float* out = (float*)d_out;

    static int configured = 0;
    if (!configured) {
        cudaFuncSetAttribute(gemm_msgs_hmma,
                             cudaFuncAttributeMaxDynamicSharedMemorySize,
                             SM_HMMA);
        configured = 1;
    }

    __half *p_wrel, *p_wq, *p_w1, *p_w2, *p_wc;
    cudaGetSymbolAddress((void**)&p_wrel, g_wrel_h);
    cudaGetSymbolAddress((void**)&p_wq, g_wq_h);
    cudaGetSymbolAddress((void**)&p_w1, g_w1_h);
    cudaGetSymbolAddress((void**)&p_w2, g_w2_h);
    cudaGetSymbolAddress((void**)&p_wc, g_wc_h);
    float *p_qrepr, *p_comb, *p_h1, *p_lin1, *p_lin2;
    cudaGetSymbolAddress((void**)&p_qrepr, g_qrepr);
    cudaGetSymbolAddress((void**)&p_comb, g_combined);
    cudaGetSymbolAddress((void**)&p_h1, g_h1);
    cudaGetSymbolAddress((void**)&p_lin1, g_lin1);
    cudaGetSymbolAddress((void**)&p_lin2, g_lin2);

    // weight conversions (tiny)
    conv_fp16_kernel<<<64, 256>>>(W_rel, p_wrel, (size_t)E_SZ * R_SZ / 4);
    conv_fp16_kernel<<<64, 256>>>(W_q, p_wq, (size_t)E_SZ * E_SZ / 4);
    conv_fp16_kernel<<<128, 256>>>(W1, p_w1, (size_t)2 * E_SZ * 4 * E_SZ / 4);
    conv_fp16_kernel<<<64, 256>>>(W2, p_w2, (size_t)E_SZ * 2 * E_SZ / 4);
    conv_fp16_kernel<<<64, 256>>>(Wc, p_wc, (size_t)HID_SZ * E_SZ / 4);

    // q_repr = e_emb @ W_q^T
    hmma_linear<<<dim3(E_SZ / 64, B_SZ / 128), 256>>>(e_emb, p_wq, nullptr, p_qrepr,
                                                      B_SZ, E_SZ, E_SZ);

    gemm_msgs_hmma<<<(B_SZ * H_SZ) / 128, 512, SM_HMMA>>>(rel, ent);

    aggregate_v2<<<B_SZ, 256>>>(e_emb, htime, qtime, maskp, log_gamma);

    // MLP1
    hmma_linear<<<dim3(HID_SZ / 64, B_SZ / 128), 256>>>(p_comb, p_w1, b1, p_lin1,
                                                        B_SZ, HID_SZ, 4 * E_SZ);
    ln_act_kernel<<<B_SZ, HID_SZ>>>(p_lin1, ln1_g, ln1_b, p_h1, HID_SZ, 1);

    // MLP2 -> dyn_emb in out[0 .. B*E)
    hmma_linear<<<dim3(E_SZ / 64, B_SZ / 128), 256>>>(p_h1, p_w2, b2, p_lin2,
                                                      B_SZ, E_SZ, HID_SZ);
    ln_act_kernel<<<B_SZ, E_SZ>>>(p_lin2, ln2_g, ln2_b, out, E_SZ, 0);

    // CTX -> out[B*E ..)
    hmma_linear<<<dim3(HID_SZ / 64, B_SZ / 128), 256>>>(out, p_wc, bc, p_lin1,
                                                        B_SZ, HID_SZ, E_SZ);
    ln_act_kernel<<<B_SZ, HID_SZ>>>(p_lin1, lnc_g, lnc_b,
                                    out + (size_t)B_SZ * E_SZ, HID_SZ, 1);
}

// round 13
// speedup vs baseline: 3.9358x; 1.1505x over previous
#include <cuda_runtime.h>
#include <cuda_fp16.h>
#include <math.h>
#include <stdint.h>

#define B_SZ   1024
#define H_SZ   200
#define E_SZ   256
#define R_SZ   256
#define HID_SZ 512
#define LN_EPS 1e-5f

// -------------------- scratch (device globals) -----------------------------
__device__ float g_msgs[(size_t)B_SZ * H_SZ * E_SZ];
__device__ float g_logits[B_SZ * H_SZ];
__device__ float g_qrepr[B_SZ * E_SZ];
__device__ float g_combined[B_SZ * 4 * E_SZ];
__device__ float g_h1[B_SZ * 2 * E_SZ];
__device__ float g_lin1[B_SZ * HID_SZ];
__device__ float g_lin2[B_SZ * E_SZ];
__device__ __half g_wrel_h[E_SZ * R_SZ];
__device__ __half g_wq_h[E_SZ * E_SZ];
__device__ __half g_w1_h[(2 * E_SZ) * (4 * E_SZ)];
__device__ __half g_w2_h[E_SZ * (2 * E_SZ)];
__device__ __half g_wc_h[HID_SZ * E_SZ];

// -------------------- helpers ----------------------------------------------
__device__ __forceinline__ uint32_t smem_to_u32(const void* p) {
    uint32_t a;
    asm("{ .reg .u64 t; cvta.to.shared.u64 t, %1; cvt.u32.u64 %0, t; }"
        : "=r"(a) : "l"(p));
    return a;
}
#define SMEM_SWIZZLE_128B(o) ((o) ^ (((o) >> 3) & 0x70))

#define LDSM_X4(r, a) \
    asm volatile("ldmatrix.sync.aligned.m8n8.x4.shared.b16 {%0,%1,%2,%3}, [%4];" \
                 : "=r"((r)[0]), "=r"((r)[1]), "=r"((r)[2]), "=r"((r)[3]) \
                 : "r"(a))

#define MMA_F16(c, a, b0, b1) \
    asm volatile("mma.sync.aligned.m16n8k16.row.col.f32.f16.f16.f32 " \
                 "{%0,%1,%2,%3}, {%4,%5,%6,%7}, {%8,%9}, {%0,%1,%2,%3};" \
                 : "+f"((c)[0]), "+f"((c)[1]), "+f"((c)[2]), "+f"((c)[3]) \
                 : "r"((a)[0]), "r"((a)[1]), "r"((a)[2]), "r"((a)[3]), \
                   "r"(b0), "r"(b1))

#define CP_ASYNC_16(dst, src) \
    asm volatile("cp.async.cg.shared.global [%0], [%1], 16;" :: "r"(dst), "l"(src))
#define CP_COMMIT() asm volatile("cp.async.commit_group;")
#define CP_WAIT0()  asm volatile("cp.async.wait_group 0;")

__device__ __forceinline__ float warpReduceSum(float v) {
#pragma unroll
    for (int o = 16; o; o >>= 1) v += __shfl_xor_sync(0xffffffffu, v, o);
    return v;
}
__device__ __forceinline__ float warpReduceMax(float v) {
#pragma unroll
    for (int o = 16; o; o >>= 1) v = fmaxf(v, __shfl_xor_sync(0xffffffffu, v, o));
    return v;
}
__device__ __forceinline__ float gelu_exact(float x) {
    return 0.5f * x * (1.0f + erff(x * 0.70710678118654752f));
}
__device__ __forceinline__ int detect_mask_mode(const void* m) {
    const unsigned char* u = (const unsigned char*)m;
    const float* f = (const float*)m;
    bool is_i = true, is_f = true;
#pragma unroll
    for (int i = 0; i < 16; i++) {
        if (u[4 * i + 1] | u[4 * i + 2] | u[4 * i + 3]) is_i = false;
        float v = f[i];
        if (v != 0.0f && v != 1.0f) is_f = false;
    }
    if (is_i) return 1;
    if (is_f) return 2;
    return 0;
}
__device__ __forceinline__ float mask_val(const void* m, int idx, int mode) {
    if (mode == 1) return ((const int*)m)[idx] != 0 ? 1.f : 0.f;
    if (mode == 2) return ((const float*)m)[idx] != 0.f ? 1.f : 0.f;
    return ((const unsigned char*)m)[idx] ? 1.f : 0.f;
}
__device__ __forceinline__ uint32_t pack_hf2(float a, float b) {
    __half2 t = __floats2half2_rn(a, b);
    return *reinterpret_cast<uint32_t*>(&t);
}

// ===========================================================================
// Kernel 0: all weight fp32 -> fp16 conversions in one launch
// segment sizes in float4 units
// ===========================================================================
#define N4_WREL (E_SZ * R_SZ / 4)
#define N4_WQ   (E_SZ * E_SZ / 4)
#define N4_W1   (2 * E_SZ * 4 * E_SZ / 4)
#define N4_W2   (E_SZ * 2 * E_SZ / 4)
#define N4_WC   (HID_SZ * E_SZ / 4)
__global__ void __launch_bounds__(256) conv_all_kernel(
        const float* __restrict__ wrel, const float* __restrict__ wq,
        const float* __restrict__ w1, const float* __restrict__ w2,
        const float* __restrict__ wc,
        __half* __restrict__ drel, __half* __restrict__ dq,
        __half* __restrict__ d1, __half* __restrict__ d2,
        __half* __restrict__ dc) {
    const size_t total = N4_WREL + N4_WQ + N4_W1 + N4_W2 + N4_WC;
    size_t i = (size_t)blockIdx.x * 256 + threadIdx.x;
    const size_t stride = (size_t)gridDim.x * 256;
    for (; i < total; i += stride) {
        const float* s;
        __half* d;
        size_t off = i;
        if (off < N4_WREL)                   { s = wrel; d = drel; }
        else if ((off -= N4_WREL) < N4_WQ)   { s = wq;   d = dq;   }
        else if ((off -= N4_WQ) < N4_W1)     { s = w1;   d = d1;   }
        else if ((off -= N4_W1) < N4_W2)     { s = w2;   d = d2;   }
        else { off -= N4_W2;                   s = wc;   d = dc;   }
        float4 x = ((const float4*)s)[off];
        ((uint2*)d)[off] = make_uint2(pack_hf2(x.x, x.y), pack_hf2(x.z, x.w));
    }
}

// ===========================================================================
// Generic HMMA linear: C[M,N] = A_f32[M,K] @ W_f16[N,K]^T (+bias)
// CTA 128(M) x 64(N), 256 thr (8 warps 4m x 2n), BK=64.
// ===========================================================================
#define HL_OA 0
#define HL_OB 16384
__global__ void __launch_bounds__(256) hmma_linear(const float* __restrict__ A,
                                                   const __half* __restrict__ W,
                                                   const float* __restrict__ bias,
                                                   float* __restrict__ C,
                                                   int M, int N, int K) {
    __shared__ char sm[16384 + 8192];
    const uint32_t smb = smem_to_u32(sm);
    const int tid = threadIdx.x;
    const int warp = tid >> 5, lane = tid & 31;
    const int wm = warp & 3, wn = warp >> 2;
    const int m0 = blockIdx.y * 128, n0 = blockIdx.x * 64;

    float acc[2][4][4];
#pragma unroll
    for (int i = 0; i < 2; i++)
#pragma unroll
        for (int j = 0; j < 4; j++)
#pragma unroll
            for (int q = 0; q < 4; q++) acc[i][j][q] = 0.f;

    for (int k0 = 0; k0 < K; k0 += 64) {
        const float* asrc = A + (size_t)m0 * K + k0;
#pragma unroll
        for (int j = 0; j < 8; j++) {
            const int idx = tid + j * 256;
            const int row = idx >> 4, c4 = idx & 15;
            float4 x = *(const float4*)(asrc + (size_t)row * K + c4 * 4);
            const int bo = SMEM_SWIZZLE_128B(row * 128 + c4 * 8);
            *(uint2*)(sm + HL_OA + bo) = make_uint2(pack_hf2(x.x, x.y), pack_hf2(x.z, x.w));
        }
        const __half* bsrc = W + (size_t)n0 * K + k0;
#pragma unroll
        for (int j = 0; j < 2; j++) {
            const int idx = tid + j * 256;
            const int row = idx >> 3, ch = idx & 7;
            const int bo = SMEM_SWIZZLE_128B(row * 128 + ch * 16);
            *(uint4*)(sm + HL_OB + bo) = *(const uint4*)(bsrc + (size_t)row * K + ch * 8);
        }
        __syncthreads();

#pragma unroll
        for (int kk = 0; kk < 4; kk++) {
            uint32_t ah[2][4];
#pragma unroll
            for (int mt = 0; mt < 2; mt++) {
                const int arow = wm * 32 + mt * 16 + (lane & 15);
                const int aoff = SMEM_SWIZZLE_128B(arow * 128 + kk * 32 + ((lane >> 4) & 1) * 16);
                LDSM_X4(ah[mt], smb + HL_OA + aoff);
            }
#pragma unroll
            for (int np = 0; np < 2; np++) {
                const int nrow = wn * 32 + np * 16 + (lane & 7) + ((lane >> 4) & 1) * 8;
                const int boff = SMEM_SWIZZLE_128B(nrow * 128 + kk * 32 + ((lane >> 3) & 1) * 16);
                uint32_t b4[4];
                LDSM_X4(b4, smb + HL_OB + boff);
#pragma unroll
                for (int mt = 0; mt < 2; mt++) {
#pragma unroll
                    for (int h = 0; h < 2; h++)
                        MMA_F16(acc[mt][np * 2 + h], ah[mt], b4[2 * h], b4[2 * h + 1]);
                }
            }
        }
        __syncthreads();
    }

    const int g = lane >> 2, tig = lane & 3;
#pragma unroll
    for (int mt = 0; mt < 2; mt++) {
        const int r0 = m0 + wm * 32 + mt * 16 + g;
        const int r1 = r0 + 8;
#pragma unroll
        for (int j = 0; j < 4; j++) {
            const int col = n0 + wn * 32 + j * 8 + tig * 2;
            float bx = 0.f, by = 0.f;
            if (bias) { bx = bias[col]; by = bias[col + 1]; }
            *(float2*)(C + (size_t)r0 * N + col) =
                make_float2(acc[mt][j][0] + bx, acc[mt][j][1] + by);
            *(float2*)(C + (size_t)r1 * N + col) =
                make_float2(acc[mt][j][2] + bx, acc[mt][j][3] + by);
        }
    }
}

// ===========================================================================
// LayerNorm (+ optional exact GELU), one row per block, blockDim == N
// ===========================================================================
__global__ void ln_act_kernel(const float* __restrict__ src, const float* __restrict__ gg,
                              const float* __restrict__ bb, float* __restrict__ dst,
                              int N, int do_gelu) {
    __shared__ float s_red[16];
    __shared__ float s_b;
    const int b = blockIdx.x, tid = threadIdx.x;
    const int wid = tid >> 5, lane = tid & 31;
    const int nw = blockDim.x >> 5;
    float x = src[(size_t)b * N + tid];
    float s = warpReduceSum(x);
    if (lane == 0) s_red[wid] = s;
    __syncthreads();
    if (tid < 32) {
        float t = (lane < nw) ? s_red[lane] : 0.f;
        t = warpReduceSum(t);
        if (lane == 0) s_b = t;
    }
    __syncthreads();
    const float mu = s_b / N;
    const float d = x - mu;
    float s2 = warpReduceSum(d * d);
    if (lane == 0) s_red[wid] = s2;
    __syncthreads();
    if (tid < 32) {
        float t = (lane < nw) ? s_red[lane] : 0.f;
        t = warpReduceSum(t);
        if (lane == 0) s_b = t;
    }
    __syncthreads();
    const float var = s_b / N;
    float y = d * rsqrtf(var + LN_EPS) * gg[tid] + bb[tid];
    dst[(size_t)b * N + tid] = do_gelu ? gelu_exact(y) : y;
}

// ===========================================================================
// Kernel B: messages + fused attention logits, double-buffered pipeline.
// CTA = 128(M) x 256(N), BK=64, 512 thr (16 warps 4m x 4n).
// A (rel fp32) pipelined through registers (cvt at STS); B via cp.async.
// smem: A0@0 (16K), A1@16K, B0@32K (32K), B1@64K  => 96KB
// ===========================================================================
#define SM_HMMA 98304

__global__ void __launch_bounds__(512, 1) gemm_msgs_hmma(const float* __restrict__ rel,
                                                         const float* __restrict__ ent) {
    extern __shared__ char sm[];
    const uint32_t smb = smem_to_u32(sm);
    const int tid = threadIdx.x;
    const int warp = tid >> 5, lane = tid & 31;
    const int wm = warp & 3, wn = warp >> 2;
    const int m0 = blockIdx.x * 128;

    float acc[2][8][4];
#pragma unroll
    for (int i = 0; i < 2; i++)
#pragma unroll
        for (int j = 0; j < 8; j++)
#pragma unroll
            for (int q = 0; q < 4; q++) acc[i][j][q] = 0.f;

    const char* wp = (const char*)g_wrel_h;

    // A-load address components (4 x float4 per thread per stage)
    const int a_row = tid >> 4;            // 0..31 (+32*j)
    const int a_c4  = tid & 15;
    // B cp.async components (4 x 16B per thread per stage)
    const int b_row = tid >> 3;            // 0..63 (+64*j)
    const int b_ch  = tid & 7;

    float4 ra[4];

    // ---- prologue: stage 0 -------------------------------------------------
    {
        const float* asrc = rel + (size_t)m0 * R_SZ;
#pragma unroll
        for (int j = 0; j < 4; j++)
            ra[j] = *(const float4*)(asrc + (size_t)(a_row + j * 32) * R_SZ + a_c4 * 4);
#pragma unroll
        for (int j = 0; j < 4; j++) {
            const int row = b_row + j * 64;
            const uint32_t dst = smb + 32768 + SMEM_SWIZZLE_128B(row * 128 + b_ch * 16);
            CP_ASYNC_16(dst, wp + (size_t)row * 512 + b_ch * 16);
        }
        CP_COMMIT();
#pragma unroll
        for (int j = 0; j < 4; j++) {
            const int bo = SMEM_SWIZZLE_128B((a_row + j * 32) * 128 + a_c4 * 8);
            *(uint2*)(sm + bo) = make_uint2(pack_hf2(ra[j].x, ra[j].y),
                                            pack_hf2(ra[j].z, ra[j].w));
        }
        CP_WAIT0();
        __syncthreads();
    }

#pragma unroll
    for (int s = 0; s < 4; s++) {
        const int cur = s & 1, nxt = (s + 1) & 1;
        // issue next-stage loads while this stage computes
        if (s < 3) {
            const float* asrc = rel + (size_t)m0 * R_SZ + (s + 1) * 64;
#pragma unroll
            for (int j = 0; j < 4; j++)
                ra[j] = *(const float4*)(asrc + (size_t)(a_row + j * 32) * R_SZ + a_c4 * 4);
            const size_t bk = (size_t)(s + 1) * 128;
#pragma unroll
            for (int j = 0; j < 4; j++) {
                const int row = b_row + j * 64;
                const uint32_t dst = smb + 32768 + nxt * 32768 +
                                     SMEM_SWIZZLE_128B(row * 128 + b_ch * 16);
                CP_ASYNC_16(dst, wp + bk + (size_t)row * 512 + b_ch * 16);
            }
            CP_COMMIT();
        }

        // ---- compute on buffer `cur` --------------------------------------
        const uint32_t abuf = smb + cur * 16384;
        const uint32_t bbuf = smb + 32768 + cur * 32768;
#pragma unroll
        for (int kk = 0; kk < 4; kk++) {
            uint32_t ah[2][4];
#pragma unroll
            for (int mt = 0; mt < 2; mt++) {
                const int arow = wm * 32 + mt * 16 + (lane & 15);
                const int aoff = SMEM_SWIZZLE_128B(arow * 128 + kk * 32 + ((lane >> 4) & 1) * 16);
                LDSM_X4(ah[mt], abuf + aoff);
            }
#pragma unroll
            for (int np = 0; np < 4; np++) {
                const int nrow = wn * 64 + np * 16 + (lane & 7) + ((lane >> 4) & 1) * 8;
                const int boff = SMEM_SWIZZLE_128B(nrow * 128 + kk * 32 + ((lane >> 3) & 1) * 16);
                uint32_t b4[4];
                LDSM_X4(b4, bbuf + boff);
#pragma unroll
                for (int mt = 0; mt < 2; mt++) {
#pragma unroll
                    for (int h = 0; h < 2; h++)
                        MMA_F16(acc[mt][np * 2 + h], ah[mt], b4[2 * h], b4[2 * h + 1]);
                }
            }
        }

        if (s < 3) {
#pragma unroll
            for (int j = 0; j < 4; j++) {
                const int bo = SMEM_SWIZZLE_128B((a_row + j * 32) * 128 + a_c4 * 8);
                *(uint2*)(sm + nxt * 16384 + bo) =
                    make_uint2(pack_hf2(ra[j].x, ra[j].y), pack_hf2(ra[j].z, ra[j].w));
            }
            CP_WAIT0();
        }
        __syncthreads();
    }

    // ---- logits staging (A buffers now free) -------------------------------
    float* s_logit = (float*)sm;               // 128 floats
    float* s_qv    = (float*)(sm + 512);       // 2 x 256 floats
    if (tid < 128) s_logit[tid] = 0.f;
    const int bA = m0 / H_SZ;
    const int bB = (m0 + 127) / H_SZ;
    {
        const int part = tid >> 8, col = tid & 255;
        const int qb = part ? bB : bA;
        s_qv[tid] = g_qrepr[qb * E_SZ + col];
    }
    __syncthreads();

    // ---- epilogue: msgs = acc*ent; per-row q-dot via smem atomics ----------
    const int g = lane >> 2, tig = lane & 3;
#pragma unroll
    for (int mt = 0; mt < 2; mt++) {
        const int lr0 = wm * 32 + mt * 16 + g;
        const int lr1 = lr0 + 8;
        const float* q0 = s_qv + (((m0 + lr0) / H_SZ == bA) ? 0 : 256);
        const float* q1 = s_qv + (((m0 + lr1) / H_SZ == bA) ? 0 : 256);
        float p0 = 0.f, p1 = 0.f;
#pragma unroll
        for (int nt = 0; nt < 8; nt++) {
            const int c = wn * 64 + nt * 8 + tig * 2;
            const size_t o1 = (size_t)(m0 + lr0) * E_SZ + c;
            const size_t o2 = (size_t)(m0 + lr1) * E_SZ + c;
            float2 e1 = *(const float2*)(ent + o1);
            float2 e2 = *(const float2*)(ent + o2);
            const float v00 = acc[mt][nt][0] * e1.x, v01 = acc[mt][nt][1] * e1.y;
            const float v10 = acc[mt][nt][2] * e2.x, v11 = acc[mt][nt][3] * e2.y;
            *(float2*)(g_msgs + o1) = make_float2(v00, v01);
            *(float2*)(g_msgs + o2) = make_float2(v10, v11);
            p0 += v00 * q0[c] + v01 * q0[c + 1];
            p1 += v10 * q1[c] + v11 * q1[c + 1];
        }
        atomicAdd(&s_logit[lr0], p0);
        atomicAdd(&s_logit[lr1], p1);
    }
    __syncthreads();
    if (tid < 128) g_logits[m0 + tid] = s_logit[tid];
}

// ===========================================================================
// Kernel C: softmax from precomputed logits + streaming PNA reductions.
// ===========================================================================
__global__ void __launch_bounds__(256) aggregate_v2(const float* __restrict__ e_emb,
                                                    const int* __restrict__ htime,
                                                    const int* __restrict__ qtime,
                                                    const void* __restrict__ maskp,
                                                    const float* __restrict__ log_gamma) {
    __shared__ float s_w[H_SZ];
    __shared__ float s_mask[H_SZ];
    __shared__ float s_red[8];
    __shared__ float s_b0, s_b1, s_b2;
    __shared__ int s_mode;

    const int b = blockIdx.x, tid = threadIdx.x;
    const int wid = tid >> 5, lane = tid & 31;

    if (tid == 0) s_mode = detect_mask_mode(maskp);
    __syncthreads();

    float lg = -INFINITY, mk = 0.f;
    if (tid < H_SZ) {
        mk = mask_val(maskp, b * H_SZ + tid, s_mode);
        s_mask[tid] = mk;
        float raw = g_logits[b * H_SZ + tid];
        float td = fmaxf((float)qtime[b] - (float)htime[b * H_SZ + tid], 0.f);
        float dec = expf(-expf(log_gamma[0]) * td);
        lg = (mk != 0.f) ? raw * dec * 0.0625f : -1e9f;
    }
    {
        float m = warpReduceMax(lg);
        if (lane == 0) s_red[wid] = m;
        __syncthreads();
        if (tid < 32) {
            float t = (lane < 8) ? s_red[lane] : -INFINITY;
            t = warpReduceMax(t);
            if (lane == 0) s_b0 = t;
        }
        __syncthreads();
    }
    const float mx = s_b0;
    float ex = (tid < H_SZ) ? expf(lg - mx) : 0.f;
    {
        float ss = warpReduceSum(ex);
        if (lane == 0) s_red[wid] = ss;
        __syncthreads();
        if (tid < 32) {
            float t = (lane < 8) ? s_red[lane] : 0.f;
            t = warpReduceSum(t);
            if (lane == 0) s_b1 = t;
        }
        __syncthreads();
        float cc = warpReduceSum(mk);
        if (lane == 0) s_red[wid] = cc;
        __syncthreads();
        if (tid < 32) {
            float t = (lane < 8) ? s_red[lane] : 0.f;
            t = warpReduceSum(t);
            if (lane == 0) s_b2 = t;
        }
        __syncthreads();
    }
    if (tid < H_SZ) s_w[tid] = ex / s_b1;
    __syncthreads();

    const float* base = g_msgs + (size_t)b * H_SZ * E_SZ + tid;
    float mean = 0.f, mxv = -INFINITY, am = 0.f;
#pragma unroll 8
    for (int h = 0; h < H_SZ; h++) {
        float val = base[(size_t)h * E_SZ];
        float m = s_mask[h];
        float vm = val * m;
        mean += vm;
        mxv = fmaxf(mxv, vm);
        am += val * s_w[h];
    }
    const float nv = fmaxf(s_b2, 1.f);
    float* outr = g_combined + (size_t)b * 4 * E_SZ;
    outr[tid]            = mean / nv;
    outr[E_SZ + tid]     = mxv;
    outr[2 * E_SZ + tid] = am;
    outr[3 * E_SZ + tid] = e_emb[b * E_SZ + tid];
}

// ===========================================================================
extern "C" void kernel_launch(void* const* d_in, const int* in_sizes, int n_in,
                              void* d_out, int out_size) {
    const float* e_emb     = (const float*)d_in[0];
    const float* ent       = (const float*)d_in[1];
    const float* rel       = (const float*)d_in[2];
    const int*   htime     = (const int*)d_in[3];
    const int*   qtime     = (const int*)d_in[4];
    const void*  maskp     = (const void*)d_in[5];
    const float* W_rel     = (const float*)d_in[6];
    const float* W_q       = (const float*)d_in[7];
    const float* log_gamma = (const float*)d_in[8];
    const float* W1        = (const float*)d_in[9];
    const float* b1        = (const float*)d_in[10];
    const float* ln1_g     = (const float*)d_in[11];
    const float* ln1_b     = (const float*)d_in[12];
    const float* W2        = (const float*)d_in[13];
    const float* b2        = (const float*)d_in[14];
    const float* ln2_g     = (const float*)d_in[15];
    const float* ln2_b     = (const float*)d_in[16];
    const float* Wc        = (const float*)d_in[17];
    const float* bc        = (const float*)d_in[18];
    const float* lnc_g     = (const float*)d_in[19];
    const float* lnc_b     = (const float*)d_in[20];
    float* out = (float*)d_out;

    static int configured = 0;
    if (!configured) {
        cudaFuncSetAttribute(gemm_msgs_hmma,
                             cudaFuncAttributeMaxDynamicSharedMemorySize,
                             SM_HMMA);
        configured = 1;
    }

    __half *p_wrel, *p_wq, *p_w1, *p_w2, *p_wc;
    cudaGetSymbolAddress((void**)&p_wrel, g_wrel_h);
    cudaGetSymbolAddress((void**)&p_wq, g_wq_h);
    cudaGetSymbolAddress((void**)&p_w1, g_w1_h);
    cudaGetSymbolAddress((void**)&p_w2, g_w2_h);
    cudaGetSymbolAddress((void**)&p_wc, g_wc_h);
    float *p_qrepr, *p_comb, *p_h1, *p_lin1, *p_lin2;
    cudaGetSymbolAddress((void**)&p_qrepr, g_qrepr);
    cudaGetSymbolAddress((void**)&p_comb, g_combined);
    cudaGetSymbolAddress((void**)&p_h1, g_h1);
    cudaGetSymbolAddress((void**)&p_lin1, g_lin1);
    cudaGetSymbolAddress((void**)&p_lin2, g_lin2);

    // all weight conversions in one kernel
    conv_all_kernel<<<448, 256>>>(W_rel, W_q, W1, W2, Wc,
                                  p_wrel, p_wq, p_w1, p_w2, p_wc);

    // q_repr = e_emb @ W_q^T
    hmma_linear<<<dim3(E_SZ / 64, B_SZ / 128), 256>>>(e_emb, p_wq, nullptr, p_qrepr,
                                                      B_SZ, E_SZ, E_SZ);

    gemm_msgs_hmma<<<(B_SZ * H_SZ) / 128, 512, SM_HMMA>>>(rel, ent);

    aggregate_v2<<<B_SZ, 256>>>(e_emb, htime, qtime, maskp, log_gamma);

    // MLP1
    hmma_linear<<<dim3(HID_SZ / 64, B_SZ / 128), 256>>>(p_comb, p_w1, b1, p_lin1,
                                                        B_SZ, HID_SZ, 4 * E_SZ);
    ln_act_kernel<<<B_SZ, HID_SZ>>>(p_lin1, ln1_g, ln1_b, p_h1, HID_SZ, 1);

    // MLP2 -> dyn_emb in out[0 .. B*E)
    hmma_linear<<<dim3(E_SZ / 64, B_SZ / 128), 256>>>(p_h1, p_w2, b2, p_lin2,
                                                      B_SZ, E_SZ, HID_SZ);
    ln_act_kernel<<<B_SZ, E_SZ>>>(p_lin2, ln2_g, ln2_b, out, E_SZ, 0);

    // CTX -> out[B*E ..)
    hmma_linear<<<dim3(HID_SZ / 64, B_SZ / 128), 256>>>(out, p_wc, bc, p_lin1,
                                                        B_SZ, HID_SZ, E_SZ);
    ln_act_kernel<<<B_SZ, HID_SZ>>>(p_lin1, lnc_g, lnc_b,
                                    out + (size_t)B_SZ * E_SZ, HID_SZ, 1);
}

// round 14
// speedup vs baseline: 4.2271x; 1.0740x over previous
#include <cuda_runtime.h>
#include <cuda_fp16.h>
#include <math.h>
#include <stdint.h>

#define B_SZ   1024
#define H_SZ   200
#define E_SZ   256
#define R_SZ   256
#define HID_SZ 512
#define LN_EPS 1e-5f

// -------------------- scratch (device globals) -----------------------------
__device__ __half g_msgs_h[(size_t)B_SZ * H_SZ * E_SZ];   // 104.9 MB fp16
__device__ float g_logits[B_SZ * H_SZ];
__device__ float g_qrepr[B_SZ * E_SZ];
__device__ float g_combined[B_SZ * 4 * E_SZ];
__device__ float g_h1[B_SZ * 2 * E_SZ];
__device__ float g_lin1[B_SZ * HID_SZ];
__device__ float g_lin2[B_SZ * E_SZ];
__device__ __half g_wrel_h[E_SZ * R_SZ];
__device__ __half g_wq_h[E_SZ * E_SZ];
__device__ __half g_w1_h[(2 * E_SZ) * (4 * E_SZ)];
__device__ __half g_w2_h[E_SZ * (2 * E_SZ)];
__device__ __half g_wc_h[HID_SZ * E_SZ];

// -------------------- helpers ----------------------------------------------
__device__ __forceinline__ uint32_t smem_to_u32(const void* p) {
    uint32_t a;
    asm("{ .reg .u64 t; cvta.to.shared.u64 t, %1; cvt.u32.u64 %0, t; }"
        : "=r"(a) : "l"(p));
    return a;
}
#define SMEM_SWIZZLE_128B(o) ((o) ^ (((o) >> 3) & 0x70))

#define LDSM_X4(r, a) \
    asm volatile("ldmatrix.sync.aligned.m8n8.x4.shared.b16 {%0,%1,%2,%3}, [%4];" \
                 : "=r"((r)[0]), "=r"((r)[1]), "=r"((r)[2]), "=r"((r)[3]) \
                 : "r"(a))

#define MMA_F16(c, a, b0, b1) \
    asm volatile("mma.sync.aligned.m16n8k16.row.col.f32.f16.f16.f32 " \
                 "{%0,%1,%2,%3}, {%4,%5,%6,%7}, {%8,%9}, {%0,%1,%2,%3};" \
                 : "+f"((c)[0]), "+f"((c)[1]), "+f"((c)[2]), "+f"((c)[3]) \
                 : "r"((a)[0]), "r"((a)[1]), "r"((a)[2]), "r"((a)[3]), \
                   "r"(b0), "r"(b1))

#define CP_ASYNC_16(dst, src) \
    asm volatile("cp.async.cg.shared.global [%0], [%1], 16;" :: "r"(dst), "l"(src))
#define CP_COMMIT() asm volatile("cp.async.commit_group;")
#define CP_WAIT0()  asm volatile("cp.async.wait_group 0;")

__device__ __forceinline__ float warpReduceSum(float v) {
#pragma unroll
    for (int o = 16; o; o >>= 1) v += __shfl_xor_sync(0xffffffffu, v, o);
    return v;
}
__device__ __forceinline__ float warpReduceMax(float v) {
#pragma unroll
    for (int o = 16; o; o >>= 1) v = fmaxf(v, __shfl_xor_sync(0xffffffffu, v, o));
    return v;
}
__device__ __forceinline__ float gelu_exact(float x) {
    return 0.5f * x * (1.0f + erff(x * 0.70710678118654752f));
}
__device__ __forceinline__ int detect_mask_mode(const void* m) {
    const unsigned char* u = (const unsigned char*)m;
    const float* f = (const float*)m;
    bool is_i = true, is_f = true;
#pragma unroll
    for (int i = 0; i < 16; i++) {
        if (u[4 * i + 1] | u[4 * i + 2] | u[4 * i + 3]) is_i = false;
        float v = f[i];
        if (v != 0.0f && v != 1.0f) is_f = false;
    }
    if (is_i) return 1;
    if (is_f) return 2;
    return 0;
}
__device__ __forceinline__ float mask_val(const void* m, int idx, int mode) {
    if (mode == 1) return ((const int*)m)[idx] != 0 ? 1.f : 0.f;
    if (mode == 2) return ((const float*)m)[idx] != 0.f ? 1.f : 0.f;
    return ((const unsigned char*)m)[idx] ? 1.f : 0.f;
}
__device__ __forceinline__ uint32_t pack_hf2(float a, float b) {
    __half2 t = __floats2half2_rn(a, b);
    return *reinterpret_cast<uint32_t*>(&t);
}

// ===========================================================================
// Kernel 0: all weight fp32 -> fp16 conversions in one launch
// ===========================================================================
#define N4_WREL (E_SZ * R_SZ / 4)
#define N4_WQ   (E_SZ * E_SZ / 4)
#define N4_W1   (2 * E_SZ * 4 * E_SZ / 4)
#define N4_W2   (E_SZ * 2 * E_SZ / 4)
#define N4_WC   (HID_SZ * E_SZ / 4)
__global__ void __launch_bounds__(256) conv_all_kernel(
        const float* __restrict__ wrel, const float* __restrict__ wq,
        const float* __restrict__ w1, const float* __restrict__ w2,
        const float* __restrict__ wc,
        __half* __restrict__ drel, __half* __restrict__ dq,
        __half* __restrict__ d1, __half* __restrict__ d2,
        __half* __restrict__ dc) {
    const size_t total = N4_WREL + N4_WQ + N4_W1 + N4_W2 + N4_WC;
    size_t i = (size_t)blockIdx.x * 256 + threadIdx.x;
    const size_t stride = (size_t)gridDim.x * 256;
    for (; i < total; i += stride) {
        const float* s;
        __half* d;
        size_t off = i;
        if (off < N4_WREL)                   { s = wrel; d = drel; }
        else if ((off -= N4_WREL) < N4_WQ)   { s = wq;   d = dq;   }
        else if ((off -= N4_WQ) < N4_W1)     { s = w1;   d = d1;   }
        else if ((off -= N4_W1) < N4_W2)     { s = w2;   d = d2;   }
        else { off -= N4_W2;                   s = wc;   d = dc;   }
        float4 x = ((const float4*)s)[off];
        ((uint2*)d)[off] = make_uint2(pack_hf2(x.x, x.y), pack_hf2(x.z, x.w));
    }
}

// ===========================================================================
// Generic HMMA linear: C[M,N] = A_f32[M,K] @ W_f16[N,K]^T (+bias)
// CTA 128(M) x 64(N), 256 thr (8 warps 4m x 2n), BK=64.
// ===========================================================================
#define HL_OA 0
#define HL_OB 16384
__global__ void __launch_bounds__(256) hmma_linear(const float* __restrict__ A,
                                                   const __half* __restrict__ W,
                                                   const float* __restrict__ bias,
                                                   float* __restrict__ C,
                                                   int M, int N, int K) {
    __shared__ char sm[16384 + 8192];
    const uint32_t smb = smem_to_u32(sm);
    const int tid = threadIdx.x;
    const int warp = tid >> 5, lane = tid & 31;
    const int wm = warp & 3, wn = warp >> 2;
    const int m0 = blockIdx.y * 128, n0 = blockIdx.x * 64;

    float acc[2][4][4];
#pragma unroll
    for (int i = 0; i < 2; i++)
#pragma unroll
        for (int j = 0; j < 4; j++)
#pragma unroll
            for (int q = 0; q < 4; q++) acc[i][j][q] = 0.f;

    for (int k0 = 0; k0 < K; k0 += 64) {
        const float* asrc = A + (size_t)m0 * K + k0;
#pragma unroll
        for (int j = 0; j < 8; j++) {
            const int idx = tid + j * 256;
            const int row = idx >> 4, c4 = idx & 15;
            float4 x = *(const float4*)(asrc + (size_t)row * K + c4 * 4);
            const int bo = SMEM_SWIZZLE_128B(row * 128 + c4 * 8);
            *(uint2*)(sm + HL_OA + bo) = make_uint2(pack_hf2(x.x, x.y), pack_hf2(x.z, x.w));
        }
        const __half* bsrc = W + (size_t)n0 * K + k0;
#pragma unroll
        for (int j = 0; j < 2; j++) {
            const int idx = tid + j * 256;
            const int row = idx >> 3, ch = idx & 7;
            const int bo = SMEM_SWIZZLE_128B(row * 128 + ch * 16);
            *(uint4*)(sm + HL_OB + bo) = *(const uint4*)(bsrc + (size_t)row * K + ch * 8);
        }
        __syncthreads();

#pragma unroll
        for (int kk = 0; kk < 4; kk++) {
            uint32_t ah[2][4];
#pragma unroll
            for (int mt = 0; mt < 2; mt++) {
                const int arow = wm * 32 + mt * 16 + (lane & 15);
                const int aoff = SMEM_SWIZZLE_128B(arow * 128 + kk * 32 + ((lane >> 4) & 1) * 16);
                LDSM_X4(ah[mt], smb + HL_OA + aoff);
            }
#pragma unroll
            for (int np = 0; np < 2; np++) {
                const int nrow = wn * 32 + np * 16 + (lane & 7) + ((lane >> 4) & 1) * 8;
                const int boff = SMEM_SWIZZLE_128B(nrow * 128 + kk * 32 + ((lane >> 3) & 1) * 16);
                uint32_t b4[4];
                LDSM_X4(b4, smb + HL_OB + boff);
#pragma unroll
                for (int mt = 0; mt < 2; mt++) {
#pragma unroll
                    for (int h = 0; h < 2; h++)
                        MMA_F16(acc[mt][np * 2 + h], ah[mt], b4[2 * h], b4[2 * h + 1]);
                }
            }
        }
        __syncthreads();
    }

    const int g = lane >> 2, tig = lane & 3;
#pragma unroll
    for (int mt = 0; mt < 2; mt++) {
        const int r0 = m0 + wm * 32 + mt * 16 + g;
        const int r1 = r0 + 8;
#pragma unroll
        for (int j = 0; j < 4; j++) {
            const int col = n0 + wn * 32 + j * 8 + tig * 2;
            float bx = 0.f, by = 0.f;
            if (bias) { bx = bias[col]; by = bias[col + 1]; }
            *(float2*)(C + (size_t)r0 * N + col) =
                make_float2(acc[mt][j][0] + bx, acc[mt][j][1] + by);
            *(float2*)(C + (size_t)r1 * N + col) =
                make_float2(acc[mt][j][2] + bx, acc[mt][j][3] + by);
        }
    }
}

// ===========================================================================
// LayerNorm (+ optional exact GELU), one row per block, blockDim == N
// ===========================================================================
__global__ void ln_act_kernel(const float* __restrict__ src, const float* __restrict__ gg,
                              const float* __restrict__ bb, float* __restrict__ dst,
                              int N, int do_gelu) {
    __shared__ float s_red[16];
    __shared__ float s_b;
    const int b = blockIdx.x, tid = threadIdx.x;
    const int wid = tid >> 5, lane = tid & 31;
    const int nw = blockDim.x >> 5;
    float x = src[(size_t)b * N + tid];
    float s = warpReduceSum(x);
    if (lane == 0) s_red[wid] = s;
    __syncthreads();
    if (tid < 32) {
        float t = (lane < nw) ? s_red[lane] : 0.f;
        t = warpReduceSum(t);
        if (lane == 0) s_b = t;
    }
    __syncthreads();
    const float mu = s_b / N;
    const float d = x - mu;
    float s2 = warpReduceSum(d * d);
    if (lane == 0) s_red[wid] = s2;
    __syncthreads();
    if (tid < 32) {
        float t = (lane < nw) ? s_red[lane] : 0.f;
        t = warpReduceSum(t);
        if (lane == 0) s_b = t;
    }
    __syncthreads();
    const float var = s_b / N;
    float y = d * rsqrtf(var + LN_EPS) * gg[tid] + bb[tid];
    dst[(size_t)b * N + tid] = do_gelu ? gelu_exact(y) : y;
}

// ===========================================================================
// Kernel B: messages (fp16 out) + fused attention logits, double-buffered.
// CTA = 128(M) x 256(N), BK=64, 512 thr (16 warps 4m x 4n).
// ===========================================================================
#define SM_HMMA 98304

__global__ void __launch_bounds__(512, 1) gemm_msgs_hmma(const float* __restrict__ rel,
                                                         const float* __restrict__ ent) {
    extern __shared__ char sm[];
    const uint32_t smb = smem_to_u32(sm);
    const int tid = threadIdx.x;
    const int warp = tid >> 5, lane = tid & 31;
    const int wm = warp & 3, wn = warp >> 2;
    const int m0 = blockIdx.x * 128;

    float acc[2][8][4];
#pragma unroll
    for (int i = 0; i < 2; i++)
#pragma unroll
        for (int j = 0; j < 8; j++)
#pragma unroll
            for (int q = 0; q < 4; q++) acc[i][j][q] = 0.f;

    const char* wp = (const char*)g_wrel_h;

    const int a_row = tid >> 4;
    const int a_c4  = tid & 15;
    const int b_row = tid >> 3;
    const int b_ch  = tid & 7;

    float4 ra[4];

    // ---- prologue: stage 0 -------------------------------------------------
    {
        const float* asrc = rel + (size_t)m0 * R_SZ;
#pragma unroll
        for (int j = 0; j < 4; j++)
            ra[j] = *(const float4*)(asrc + (size_t)(a_row + j * 32) * R_SZ + a_c4 * 4);
#pragma unroll
        for (int j = 0; j < 4; j++) {
            const int row = b_row + j * 64;
            const uint32_t dst = smb + 32768 + SMEM_SWIZZLE_128B(row * 128 + b_ch * 16);
            CP_ASYNC_16(dst, wp + (size_t)row * 512 + b_ch * 16);
        }
        CP_COMMIT();
#pragma unroll
        for (int j = 0; j < 4; j++) {
            const int bo = SMEM_SWIZZLE_128B((a_row + j * 32) * 128 + a_c4 * 8);
            *(uint2*)(sm + bo) = make_uint2(pack_hf2(ra[j].x, ra[j].y),
                                            pack_hf2(ra[j].z, ra[j].w));
        }
        CP_WAIT0();
        __syncthreads();
    }

#pragma unroll
    for (int s = 0; s < 4; s++) {
        const int cur = s & 1, nxt = (s + 1) & 1;
        if (s < 3) {
            const float* asrc = rel + (size_t)m0 * R_SZ + (s + 1) * 64;
#pragma unroll
            for (int j = 0; j < 4; j++)
                ra[j] = *(const float4*)(asrc + (size_t)(a_row + j * 32) * R_SZ + a_c4 * 4);
            const size_t bk = (size_t)(s + 1) * 128;
#pragma unroll
            for (int j = 0; j < 4; j++) {
                const int row = b_row + j * 64;
                const uint32_t dst = smb + 32768 + nxt * 32768 +
                                     SMEM_SWIZZLE_128B(row * 128 + b_ch * 16);
                CP_ASYNC_16(dst, wp + bk + (size_t)row * 512 + b_ch * 16);
            }
            CP_COMMIT();
        }

        const uint32_t abuf = smb + cur * 16384;
        const uint32_t bbuf = smb + 32768 + cur * 32768;
#pragma unroll
        for (int kk = 0; kk < 4; kk++) {
            uint32_t ah[2][4];
#pragma unroll
            for (int mt = 0; mt < 2; mt++) {
                const int arow = wm * 32 + mt * 16 + (lane & 15);
                const int aoff = SMEM_SWIZZLE_128B(arow * 128 + kk * 32 + ((lane >> 4) & 1) * 16);
                LDSM_X4(ah[mt], abuf + aoff);
            }
#pragma unroll
            for (int np = 0; np < 4; np++) {
                const int nrow = wn * 64 + np * 16 + (lane & 7) + ((lane >> 4) & 1) * 8;
                const int boff = SMEM_SWIZZLE_128B(nrow * 128 + kk * 32 + ((lane >> 3) & 1) * 16);
                uint32_t b4[4];
                LDSM_X4(b4, bbuf + boff);
#pragma unroll
                for (int mt = 0; mt < 2; mt++) {
#pragma unroll
                    for (int h = 0; h < 2; h++)
                        MMA_F16(acc[mt][np * 2 + h], ah[mt], b4[2 * h], b4[2 * h + 1]);
                }
            }
        }

        if (s < 3) {
#pragma unroll
            for (int j = 0; j < 4; j++) {
                const int bo = SMEM_SWIZZLE_128B((a_row + j * 32) * 128 + a_c4 * 8);
                *(uint2*)(sm + nxt * 16384 + bo) =
                    make_uint2(pack_hf2(ra[j].x, ra[j].y), pack_hf2(ra[j].z, ra[j].w));
            }
            CP_WAIT0();
        }
        __syncthreads();
    }

    // ---- logits staging (A buffers now free) -------------------------------
    float* s_logit = (float*)sm;               // 128 floats
    float* s_qv    = (float*)(sm + 512);       // 2 x 256 floats
    if (tid < 128) s_logit[tid] = 0.f;
    const int bA = m0 / H_SZ;
    const int bB = (m0 + 127) / H_SZ;
    {
        const int part = tid >> 8, col = tid & 255;
        const int qb = part ? bB : bA;
        s_qv[tid] = g_qrepr[qb * E_SZ + col];
    }
    __syncthreads();

    // ---- epilogue: batched ent loads, msgs fp16 store, fused q-dot ---------
    const int g = lane >> 2, tig = lane & 3;
#pragma unroll
    for (int mt = 0; mt < 2; mt++) {
        const int lr0 = wm * 32 + mt * 16 + g;
        const int lr1 = lr0 + 8;
        const float* q0 = s_qv + (((m0 + lr0) / H_SZ == bA) ? 0 : 256);
        const float* q1 = s_qv + (((m0 + lr1) / H_SZ == bA) ? 0 : 256);
        const size_t rb0 = (size_t)(m0 + lr0) * E_SZ;
        const size_t rb1 = (size_t)(m0 + lr1) * E_SZ;
        // batch all ent loads first (memory-level parallelism)
        float2 e1[8], e2[8];
#pragma unroll
        for (int nt = 0; nt < 8; nt++) {
            const int c = wn * 64 + nt * 8 + tig * 2;
            e1[nt] = *(const float2*)(ent + rb0 + c);
            e2[nt] = *(const float2*)(ent + rb1 + c);
        }
        float p0 = 0.f, p1 = 0.f;
#pragma unroll
        for (int nt = 0; nt < 8; nt++) {
            const int c = wn * 64 + nt * 8 + tig * 2;
            const float v00 = acc[mt][nt][0] * e1[nt].x, v01 = acc[mt][nt][1] * e1[nt].y;
            const float v10 = acc[mt][nt][2] * e2[nt].x, v11 = acc[mt][nt][3] * e2[nt].y;
            *(uint32_t*)(g_msgs_h + rb0 + c) = pack_hf2(v00, v01);
            *(uint32_t*)(g_msgs_h + rb1 + c) = pack_hf2(v10, v11);
            p0 += v00 * q0[c] + v01 * q0[c + 1];
            p1 += v10 * q1[c] + v11 * q1[c + 1];
        }
        atomicAdd(&s_logit[lr0], p0);
        atomicAdd(&s_logit[lr1], p1);
    }
    __syncthreads();
    if (tid < 128) g_logits[m0 + tid] = s_logit[tid];
}

// ===========================================================================
// Kernel C: softmax from precomputed logits + streaming PNA reductions (fp16)
// ===========================================================================
__global__ void __launch_bounds__(256) aggregate_v2(const float* __restrict__ e_emb,
                                                    const int* __restrict__ htime,
                                                    const int* __restrict__ qtime,
                                                    const void* __restrict__ maskp,
                                                    const float* __restrict__ log_gamma) {
    __shared__ float s_w[H_SZ];
    __shared__ float s_mask[H_SZ];
    __shared__ float s_red[8];
    __shared__ float s_b0, s_b1, s_b2;
    __shared__ int s_mode;

    const int b = blockIdx.x, tid = threadIdx.x;
    const int wid = tid >> 5, lane = tid & 31;

    if (tid == 0) s_mode = detect_mask_mode(maskp);
    __syncthreads();

    float lg = -INFINITY, mk = 0.f;
    if (tid < H_SZ) {
        mk = mask_val(maskp, b * H_SZ + tid, s_mode);
        s_mask[tid] = mk;
        float raw = g_logits[b * H_SZ + tid];
        float td = fmaxf((float)qtime[b] - (float)htime[b * H_SZ + tid], 0.f);
        float dec = expf(-expf(log_gamma[0]) * td);
        lg = (mk != 0.f) ? raw * dec * 0.0625f : -1e9f;
    }
    {
        float m = warpReduceMax(lg);
        if (lane == 0) s_red[wid] = m;
        __syncthreads();
        if (tid < 32) {
            float t = (lane < 8) ? s_red[lane] : -INFINITY;
            t = warpReduceMax(t);
            if (lane == 0) s_b0 = t;
        }
        __syncthreads();
    }
    const float mx = s_b0;
    float ex = (tid < H_SZ) ? expf(lg - mx) : 0.f;
    {
        float ss = warpReduceSum(ex);
        if (lane == 0) s_red[wid] = ss;
        __syncthreads();
        if (tid < 32) {
            float t = (lane < 8) ? s_red[lane] : 0.f;
            t = warpReduceSum(t);
            if (lane == 0) s_b1 = t;
        }
        __syncthreads();
        float cc = warpReduceSum(mk);
        if (lane == 0) s_red[wid] = cc;
        __syncthreads();
        if (tid < 32) {
            float t = (lane < 8) ? s_red[lane] : 0.f;
            t = warpReduceSum(t);
            if (lane == 0) s_b2 = t;
        }
        __syncthreads();
    }
    if (tid < H_SZ) s_w[tid] = ex / s_b1;
    __syncthreads();

    const __half* base = g_msgs_h + (size_t)b * H_SZ * E_SZ + tid;
    float mean = 0.f, mxv = -INFINITY, am = 0.f;
#pragma unroll 8
    for (int h = 0; h < H_SZ; h++) {
        float val = __half2float(base[(size_t)h * E_SZ]);
        float m = s_mask[h];
        float vm = val * m;
        mean += vm;
        mxv = fmaxf(mxv, vm);
        am += val * s_w[h];
    }
    const float nv = fmaxf(s_b2, 1.f);
    float* outr = g_combined + (size_t)b * 4 * E_SZ;
    outr[tid]            = mean / nv;
    outr[E_SZ + tid]     = mxv;
    outr[2 * E_SZ + tid] = am;
    outr[3 * E_SZ + tid] = e_emb[b * E_SZ + tid];
}

// ===========================================================================
extern "C" void kernel_launch(void* const* d_in, const int* in_sizes, int n_in,
                              void* d_out, int out_size) {
    const float* e_emb     = (const float*)d_in[0];
    const float* ent       = (const float*)d_in[1];
    const float* rel       = (const float*)d_in[2];
    const int*   htime     = (const int*)d_in[3];
    const int*   qtime     = (const int*)d_in[4];
    const void*  maskp     = (const void*)d_in[5];
    const float* W_rel     = (const float*)d_in[6];
    const float* W_q       = (const float*)d_in[7];
    const float* log_gamma = (const float*)d_in[8];
    const float* W1        = (const float*)d_in[9];
    const float* b1        = (const float*)d_in[10];
    const float* ln1_g     = (const float*)d_in[11];
    const float* ln1_b     = (const float*)d_in[12];
    const float* W2        = (const float*)d_in[13];
    const float* b2        = (const float*)d_in[14];
    const float* ln2_g     = (const float*)d_in[15];
    const float* ln2_b     = (const float*)d_in[16];
    const float* Wc        = (const float*)d_in[17];
    const float* bc        = (const float*)d_in[18];
    const float* lnc_g     = (const float*)d_in[19];
    const float* lnc_b     = (const float*)d_in[20];
    float* out = (float*)d_out;

    static int configured = 0;
    if (!configured) {
        cudaFuncSetAttribute(gemm_msgs_hmma,
                             cudaFuncAttributeMaxDynamicSharedMemorySize,
                             SM_HMMA);
        configured = 1;
    }

    __half *p_wrel, *p_wq, *p_w1, *p_w2, *p_wc;
    cudaGetSymbolAddress((void**)&p_wrel, g_wrel_h);
    cudaGetSymbolAddress((void**)&p_wq, g_wq_h);
    cudaGetSymbolAddress((void**)&p_w1, g_w1_h);
    cudaGetSymbolAddress((void**)&p_w2, g_w2_h);
    cudaGetSymbolAddress((void**)&p_wc, g_wc_h);
    float *p_qrepr, *p_comb, *p_h1, *p_lin1, *p_lin2;
    cudaGetSymbolAddress((void**)&p_qrepr, g_qrepr);
    cudaGetSymbolAddress((void**)&p_comb, g_combined);
    cudaGetSymbolAddress((void**)&p_h1, g_h1);
    cudaGetSymbolAddress((void**)&p_lin1, g_lin1);
    cudaGetSymbolAddress((void**)&p_lin2, g_lin2);

    conv_all_kernel<<<448, 256>>>(W_rel, W_q, W1, W2, Wc,
                                  p_wrel, p_wq, p_w1, p_w2, p_wc);

    // q_repr = e_emb @ W_q^T
    hmma_linear<<<dim3(E_SZ / 64, B_SZ / 128), 256>>>(e_emb, p_wq, nullptr, p_qrepr,
                                                      B_SZ, E_SZ, E_SZ);

    gemm_msgs_hmma<<<(B_SZ * H_SZ) / 128, 512, SM_HMMA>>>(rel, ent);

    aggregate_v2<<<B_SZ, 256>>>(e_emb, htime, qtime, maskp, log_gamma);

    // MLP1
    hmma_linear<<<dim3(HID_SZ / 64, B_SZ / 128), 256>>>(p_comb, p_w1, b1, p_lin1,
                                                        B_SZ, HID_SZ, 4 * E_SZ);
    ln_act_kernel<<<B_SZ, HID_SZ>>>(p_lin1, ln1_g, ln1_b, p_h1, HID_SZ, 1);

    // MLP2 -> dyn_emb in out[0 .. B*E)
    hmma_linear<<<dim3(E_SZ / 64, B_SZ / 128), 256>>>(p_h1, p_w2, b2, p_lin2,
                                                      B_SZ, E_SZ, HID_SZ);
    ln_act_kernel<<<B_SZ, E_SZ>>>(p_lin2, ln2_g, ln2_b, out, E_SZ, 0);

    // CTX -> out[B*E ..)
    hmma_linear<<<dim3(HID_SZ / 64, B_SZ / 128), 256>>>(out, p_wc, bc, p_lin1,
                                                        B_SZ, HID_SZ, E_SZ);
    ln_act_kernel<<<B_SZ, HID_SZ>>>(p_lin1, lnc_g, lnc_b,
                                    out + (size_t)B_SZ * E_SZ, HID_SZ, 1);
}